// round 11
// baseline (speedup 1.0000x reference)
#include <cuda_runtime.h>
#include <cuda_bf16.h>
#include <math.h>
#include <stdint.h>

#define TOK 4096      // B*N = 2*2048
#define DM  1024
#define SEQ 2048
#define NHEAD 16

// ---------------- scratch (no cudaMalloc allowed) ----------------
__device__ float g_x1  [TOK * DM];

__device__ __nv_bfloat16 g_qkvw_hi[3 * DM * DM], g_qkvw_lo[3 * DM * DM];
__device__ __nv_bfloat16 g_ow_hi  [DM * DM],     g_ow_lo  [DM * DM];
__device__ __nv_bfloat16 g_w1_hi  [4 * DM * DM], g_w1_lo  [4 * DM * DM];
__device__ __nv_bfloat16 g_w2_hi  [4 * DM * DM], g_w2_lo  [4 * DM * DM];
__device__ __nv_bfloat16 g_h_hi   [TOK * DM],    g_h_lo   [TOK * DM];
__device__ __nv_bfloat16 g_qkv_hi [TOK * 3 * DM],g_qkv_lo [TOK * 3 * DM];
__device__ __nv_bfloat16 g_at_hi  [TOK * DM],    g_at_lo  [TOK * DM];
__device__ __nv_bfloat16 g_h2_hi  [TOK * DM],    g_h2_lo  [TOK * DM];
__device__ __nv_bfloat16 g_f1_hi  [TOK * 4 * DM],g_f1_lo  [TOK * 4 * DM];

// ---------------- helpers ----------------
__device__ __forceinline__ uint32_t smem_u32(const void* p) {
    uint32_t a;
    asm("{ .reg .u64 t; cvta.to.shared.u64 t, %1; cvt.u32.u64 %0, t; }" : "=r"(a) : "l"(p));
    return a;
}
#define CP_ASYNC16(sa, ga) \
    asm volatile("cp.async.cg.shared.global [%0], [%1], 16;" :: "r"(sa), "l"(ga))
#define CP_COMMIT() asm volatile("cp.async.commit_group;" ::: "memory")
#define CP_WAIT1()  asm volatile("cp.async.wait_group 1;" ::: "memory")

__device__ __forceinline__ void ldsm4(uint32_t* r, uint32_t addr) {
    asm volatile("ldmatrix.sync.aligned.m8n8.x4.shared.b16 {%0,%1,%2,%3}, [%4];"
                 : "=r"(r[0]), "=r"(r[1]), "=r"(r[2]), "=r"(r[3]) : "r"(addr));
}
__device__ __forceinline__ void ldsm4t(uint32_t* r, uint32_t addr) {
    asm volatile("ldmatrix.sync.aligned.m8n8.x4.trans.shared.b16 {%0,%1,%2,%3}, [%4];"
                 : "=r"(r[0]), "=r"(r[1]), "=r"(r[2]), "=r"(r[3]) : "r"(addr));
}
__device__ __forceinline__ void mma16816(float* d, const uint32_t* a, uint32_t b0, uint32_t b1) {
    asm volatile("mma.sync.aligned.m16n8k16.row.col.f32.bf16.bf16.f32 "
                 "{%0,%1,%2,%3}, {%4,%5,%6,%7}, {%8,%9}, {%0,%1,%2,%3};"
                 : "+f"(d[0]), "+f"(d[1]), "+f"(d[2]), "+f"(d[3])
                 : "r"(a[0]), "r"(a[1]), "r"(a[2]), "r"(a[3]), "r"(b0), "r"(b1));
}
__device__ __forceinline__ void split_f(float v, __nv_bfloat16& h, __nv_bfloat16& l) {
    h = __float2bfloat16(v);
    l = __float2bfloat16(v - __bfloat162float(h));
}

// ---------------- fp32 -> bf16 hi/lo split (weights only) ----------------
__global__ __launch_bounds__(256) void split4(const float4* __restrict__ in,
                                              __nv_bfloat162* __restrict__ hi,
                                              __nv_bfloat162* __restrict__ lo, int n4)
{
    int i = blockIdx.x * 256 + threadIdx.x;
    if (i >= n4) return;
    float4 x = in[i];
    __nv_bfloat16 h0, l0, h1, l1, h2, l2, h3, l3;
    split_f(x.x, h0, l0); split_f(x.y, h1, l1);
    split_f(x.z, h2, l2); split_f(x.w, h3, l3);
    hi[2 * i]     = __nv_bfloat162(h0, h1);
    hi[2 * i + 1] = __nv_bfloat162(h2, h3);
    lo[2 * i]     = __nv_bfloat162(l0, l1);
    lo[2 * i + 1] = __nv_bfloat162(l2, l3);
}

// ---------------- LayerNorm -> bf16 hi/lo ----------------
__global__ __launch_bounds__(256) void ln_split(const float* __restrict__ x,
                                                const float* __restrict__ w,
                                                const float* __restrict__ b,
                                                __nv_bfloat16* __restrict__ ohi,
                                                __nv_bfloat16* __restrict__ olo)
{
    int row = blockIdx.x;
    const float* xr = x + (size_t)row * DM;
    float v[4];
    float sum = 0.f, sq = 0.f;
#pragma unroll
    for (int k = 0; k < 4; k++) {
        v[k] = xr[threadIdx.x + 256 * k];
        sum += v[k];
        sq  += v[k] * v[k];
    }
#pragma unroll
    for (int o = 16; o > 0; o >>= 1) {
        sum += __shfl_xor_sync(0xffffffffu, sum, o);
        sq  += __shfl_xor_sync(0xffffffffu, sq, o);
    }
    __shared__ float ssum[8], ssq[8], s_mu, s_rinv;
    int wid = threadIdx.x >> 5, lid = threadIdx.x & 31;
    if (lid == 0) { ssum[wid] = sum; ssq[wid] = sq; }
    __syncthreads();
    if (threadIdx.x == 0) {
        float ts = 0.f, tq = 0.f;
#pragma unroll
        for (int i = 0; i < 8; i++) { ts += ssum[i]; tq += ssq[i]; }
        float mu  = ts * (1.0f / DM);
        float var = tq * (1.0f / DM) - mu * mu;
        s_mu = mu; s_rinv = rsqrtf(var + 1e-5f);
    }
    __syncthreads();
    float mu = s_mu, rinv = s_rinv;
#pragma unroll
    for (int k = 0; k < 4; k++) {
        int c = threadIdx.x + 256 * k;
        float val = (v[k] - mu) * rinv * w[c] + b[c];
        __nv_bfloat16 h, l;
        split_f(val, h, l);
        ohi[(size_t)row * DM + c] = h;
        olo[(size_t)row * DM + c] = l;
    }
}

// ---------------- mma.sync GEMM: C[M,N] = A[M,K] @ W[N,K]^T ----------------
#define BK 32
#define MAT_B (128 * 40 * 2)           // 10240 bytes per matrix tile (80B rows)
#define STG_B (4 * MAT_B)
#define SMEM_TOT (2 * STG_B)

__global__ __launch_bounds__(256, 1) void gemm_mma(
    const __nv_bfloat16* __restrict__ Ah, const __nv_bfloat16* __restrict__ Al,
    const __nv_bfloat16* __restrict__ Wh, const __nv_bfloat16* __restrict__ Wl,
    const float* __restrict__ bias, const float* __restrict__ res,
    float* __restrict__ C,
    __nv_bfloat16* __restrict__ Chi, __nv_bfloat16* __restrict__ Clo,
    int N, int K, int do_gelu)
{
    extern __shared__ char smem[];
    uint32_t sbase = smem_u32(smem);
    int t = threadIdx.x;
    int w = t >> 5, lane = t & 31;
    int warp_m = w & 1, warp_n = w >> 1;
    int lr = lane & 15, lh = lane >> 4;

    int row0 = blockIdx.y * 128;
    int col0 = blockIdx.x * 128;
    const __nv_bfloat16* srcs[4] = {
        Ah + (size_t)row0 * K, Al + (size_t)row0 * K,
        Wh + (size_t)col0 * K, Wl + (size_t)col0 * K };

    float acc[4][4][4];
#pragma unroll
    for (int i = 0; i < 4; i++)
#pragma unroll
        for (int j = 0; j < 4; j++)
#pragma unroll
            for (int q = 0; q < 4; q++) acc[i][j][q] = 0.f;

    int niter = K / BK;

    {
        uint32_t sst = sbase;
#pragma unroll
        for (int c8 = 0; c8 < 8; c8++) {
            int c = c8 * 256 + t;
            int mat = c >> 9, rem = c & 511, r = rem >> 2, q = rem & 3;
            CP_ASYNC16(sst + mat * MAT_B + r * 80 + q * 16,
                       srcs[mat] + (size_t)r * K + q * 8);
        }
        CP_COMMIT();
    }

    for (int it = 0; it < niter; it++) {
        if (it + 1 < niter) {
            uint32_t sst = sbase + ((it + 1) & 1) * STG_B;
            int k0 = (it + 1) * BK;
#pragma unroll
            for (int c8 = 0; c8 < 8; c8++) {
                int c = c8 * 256 + t;
                int mat = c >> 9, rem = c & 511, r = rem >> 2, q = rem & 3;
                CP_ASYNC16(sst + mat * MAT_B + r * 80 + q * 16,
                           srcs[mat] + (size_t)r * K + k0 + q * 8);
            }
        }
        CP_COMMIT();
        CP_WAIT1();
        __syncthreads();

        uint32_t sst = sbase + (it & 1) * STG_B;
#pragma unroll
        for (int ks = 0; ks < 2; ks++) {
            uint32_t coff = ks * 32 + lh * 16;
            uint32_t ah[4][4], al[4][4], bh[2][4], bl[2][4];
#pragma unroll
            for (int mt = 0; mt < 4; mt++) {
                uint32_t rofs = (warp_m * 64 + mt * 16 + lr) * 80 + coff;
                ldsm4(ah[mt], sst + rofs);
                ldsm4(al[mt], sst + MAT_B + rofs);
            }
#pragma unroll
            for (int p = 0; p < 2; p++) {
                uint32_t rofs = (warp_n * 32 + p * 16 + lr) * 80 + coff;
                ldsm4(bh[p], sst + 2 * MAT_B + rofs);
                ldsm4(bl[p], sst + 3 * MAT_B + rofs);
            }
#pragma unroll
            for (int mt = 0; mt < 4; mt++)
#pragma unroll
                for (int nt = 0; nt < 4; nt++) {
                    int p = nt >> 1, o = nt & 1;
                    mma16816(acc[mt][nt], ah[mt], bh[p][o], bh[p][o + 2]);
                }
#pragma unroll
            for (int mt = 0; mt < 4; mt++)
#pragma unroll
                for (int nt = 0; nt < 4; nt++) {
                    int p = nt >> 1, o = nt & 1;
                    mma16816(acc[mt][nt], ah[mt], bl[p][o], bl[p][o + 2]);
                }
#pragma unroll
            for (int mt = 0; mt < 4; mt++)
#pragma unroll
                for (int nt = 0; nt < 4; nt++) {
                    int p = nt >> 1, o = nt & 1;
                    mma16816(acc[mt][nt], al[mt], bh[p][o], bh[p][o + 2]);
                }
        }
        __syncthreads();
    }

    int g = lane >> 2, tig = lane & 3;
#pragma unroll
    for (int mt = 0; mt < 4; mt++) {
#pragma unroll
        for (int nt = 0; nt < 4; nt++) {
            int col = col0 + warp_n * 32 + nt * 8 + tig * 2;
            float b0 = 0.f, b1 = 0.f;
            if (bias) { b0 = bias[col]; b1 = bias[col + 1]; }
#pragma unroll
            for (int hrow = 0; hrow < 2; hrow++) {
                int row = row0 + warp_m * 64 + mt * 16 + g + hrow * 8;
                float vx = acc[mt][nt][hrow * 2]     + b0;
                float vy = acc[mt][nt][hrow * 2 + 1] + b1;
                if (do_gelu) {
                    vx = 0.5f * vx * (1.f + erff(vx * 0.70710678f));
                    vy = 0.5f * vy * (1.f + erff(vy * 0.70710678f));
                }
                if (res) {
                    vx += res[(size_t)row * N + col];
                    vy += res[(size_t)row * N + col + 1];
                }
                if (C) {
                    *(float2*)(C + (size_t)row * N + col) = make_float2(vx, vy);
                }
                if (Chi) {
                    __nv_bfloat16 hx, lx, hy, ly;
                    split_f(vx, hx, lx); split_f(vy, hy, ly);
                    *(__nv_bfloat162*)(Chi + (size_t)row * N + col) = __nv_bfloat162(hx, hy);
                    *(__nv_bfloat162*)(Clo + (size_t)row * N + col) = __nv_bfloat162(lx, ly);
                }
            }
        }
    }
}

// ---------------- tensor-core causal flash attention ----------------
// BM=64 q-rows/CTA, 4 warps x 16 rows; kv tiles of 64 double-buffered.
// Full split precision: S = Qh*Kh + Qh*Kl + Ql*Kh ; O += Ph*Vh + Ph*Vl + Pl*Vh
#define ARS   144                     // smem row bytes (64*2 + 16 pad)
#define ATB   (64 * ARS)              // 9216 per matrix
#define AQ_B  (2 * ATB)               // Qh, Ql
#define ASTG  (4 * ATB)               // Kh, Kl, Vh, Vl
#define ASM_TOT (AQ_B + 2 * ASTG)     // 92160

__global__ __launch_bounds__(128) void attn_mma(
    const __nv_bfloat16* __restrict__ qkvh, const __nv_bfloat16* __restrict__ qkvl,
    __nv_bfloat16* __restrict__ ohi, __nv_bfloat16* __restrict__ olo)
{
    extern __shared__ char smem[];
    uint32_t sb = smem_u32(smem);
    int t = threadIdx.x, w = t >> 5, lane = t & 31;
    int qt = blockIdx.x, head = blockIdx.y, b = blockIdx.z;
    int q0 = qt * 64;

    // ldmatrix x4 address patterns (relative row/col within a 16x16 block)
    int a_row = (lane & 7) + ((lane & 8) ? 8 : 0);    // a-style / V-trans
    int a_cb  = (lane & 16) ? 16 : 0;
    int b_row = (lane & 7) + ((lane & 16) ? 8 : 0);   // K b-style (no trans)
    int b_cb  = (lane & 8) ? 16 : 0;

    // ---- load Q (hi/lo) ----
#pragma unroll
    for (int i = 0; i < 8; i++) {
        int c = i * 128 + t;
        int mat = c >> 9, rem = c & 511, r = rem >> 3, c16 = rem & 7;
        const __nv_bfloat16* src = (mat ? qkvl : qkvh) +
            ((size_t)(b * SEQ + q0 + r) * (3 * DM) + head * 64 + c16 * 8);
        CP_ASYNC16(sb + mat * ATB + r * ARS + c16 * 16, src);
    }
    CP_COMMIT();

    // ---- prefetch kv tile 0 ----
    {
        uint32_t sst = sb + AQ_B;
#pragma unroll
        for (int i = 0; i < 16; i++) {
            int c = i * 128 + t;
            int mat = c >> 9, rem = c & 511, r = rem >> 3, c16 = rem & 7;
            const __nv_bfloat16* base = (mat & 1) ? qkvl : qkvh;
            int off = (mat >> 1) ? 2 * DM : DM;
            const __nv_bfloat16* src = base +
                ((size_t)(b * SEQ + r) * (3 * DM) + off + head * 64 + c16 * 8);
            CP_ASYNC16(sst + mat * ATB + r * ARS + c16 * 16, src);
        }
        CP_COMMIT();
    }

    uint32_t qa_h[4][4], qa_l[4][4];
    float of[8][4];
#pragma unroll
    for (int f = 0; f < 8; f++)
#pragma unroll
        for (int q = 0; q < 4; q++) of[f][q] = 0.f;
    float m0 = -1e30f, m1 = -1e30f, l0 = 0.f, l1 = 0.f;

    int row_in0 = (lane >> 2);          // 0..7
    int colb2   = 2 * (lane & 3);       // 0,2,4,6

    for (int kt = 0; kt <= qt; kt++) {
        // prefetch next
        if (kt < qt) {
            uint32_t sst = sb + AQ_B + ((kt + 1) & 1) * ASTG;
            int k0n = (kt + 1) * 64;
#pragma unroll
            for (int i = 0; i < 16; i++) {
                int c = i * 128 + t;
                int mat = c >> 9, rem = c & 511, r = rem >> 3, c16 = rem & 7;
                const __nv_bfloat16* base = (mat & 1) ? qkvl : qkvh;
                int off = (mat >> 1) ? 2 * DM : DM;
                const __nv_bfloat16* src = base +
                    ((size_t)(b * SEQ + k0n + r) * (3 * DM) + off + head * 64 + c16 * 8);
                CP_ASYNC16(sst + mat * ATB + r * ARS + c16 * 16, src);
            }
        }
        CP_COMMIT();
        CP_WAIT1();
        __syncthreads();

        if (kt == 0) {
            // load Q fragments once
#pragma unroll
            for (int ks = 0; ks < 4; ks++) {
                uint32_t ao = (uint32_t)((w * 16 + a_row) * ARS + ks * 32 + a_cb);
                ldsm4(qa_h[ks], sb + ao);
                ldsm4(qa_l[ks], sb + ATB + ao);
            }
        }

        uint32_t kst = sb + AQ_B + (kt & 1) * ASTG;

        // ---- S = Q K^T (3 passes) ----
        float sf[8][4];
#pragma unroll
        for (int f = 0; f < 8; f++)
#pragma unroll
            for (int q = 0; q < 4; q++) sf[f][q] = 0.f;

#pragma unroll
        for (int ks = 0; ks < 4; ks++) {
#pragma unroll
            for (int nb = 0; nb < 4; nb++) {
                uint32_t ko = (uint32_t)((nb * 16 + b_row) * ARS + ks * 32 + b_cb);
                uint32_t kh4[4], kl4[4];
                ldsm4(kh4, kst + ko);
                ldsm4(kl4, kst + ATB + ko);
                mma16816(sf[2 * nb],     qa_h[ks], kh4[0], kh4[1]);
                mma16816(sf[2 * nb + 1], qa_h[ks], kh4[2], kh4[3]);
                mma16816(sf[2 * nb],     qa_h[ks], kl4[0], kl4[1]);
                mma16816(sf[2 * nb + 1], qa_h[ks], kl4[2], kl4[3]);
                mma16816(sf[2 * nb],     qa_l[ks], kh4[0], kh4[1]);
                mma16816(sf[2 * nb + 1], qa_l[ks], kh4[2], kh4[3]);
            }
        }

        // ---- scale + causal mask ----
        int r0 = q0 + w * 16 + row_in0;
        int r1 = r0 + 8;
        int k0 = kt * 64;
#pragma unroll
        for (int f = 0; f < 8; f++) {
#pragma unroll
            for (int q = 0; q < 4; q++) sf[f][q] *= 0.125f;
            if (kt == qt) {
                int c0 = k0 + f * 8 + colb2;
                if (c0 > r0)     sf[f][0] = -1e30f;
                if (c0 + 1 > r0) sf[f][1] = -1e30f;
                if (c0 > r1)     sf[f][2] = -1e30f;
                if (c0 + 1 > r1) sf[f][3] = -1e30f;
            }
        }

        // ---- online softmax ----
        float mx0 = -1e30f, mx1 = -1e30f;
#pragma unroll
        for (int f = 0; f < 8; f++) {
            mx0 = fmaxf(mx0, fmaxf(sf[f][0], sf[f][1]));
            mx1 = fmaxf(mx1, fmaxf(sf[f][2], sf[f][3]));
        }
        mx0 = fmaxf(mx0, __shfl_xor_sync(0xffffffffu, mx0, 1));
        mx0 = fmaxf(mx0, __shfl_xor_sync(0xffffffffu, mx0, 2));
        mx1 = fmaxf(mx1, __shfl_xor_sync(0xffffffffu, mx1, 1));
        mx1 = fmaxf(mx1, __shfl_xor_sync(0xffffffffu, mx1, 2));
        float mn0 = fmaxf(m0, mx0), mn1 = fmaxf(m1, mx1);
        float cr0 = __expf(m0 - mn0), cr1 = __expf(m1 - mn1);
        m0 = mn0; m1 = mn1;
        l0 *= cr0; l1 *= cr1;
#pragma unroll
        for (int f = 0; f < 8; f++) {
            of[f][0] *= cr0; of[f][1] *= cr0;
            of[f][2] *= cr1; of[f][3] *= cr1;
        }

        uint32_t ph[4][4], pl[4][4];
#pragma unroll
        for (int f = 0; f < 8; f++) {
            float p0 = __expf(sf[f][0] - mn0);
            float p1 = __expf(sf[f][1] - mn0);
            float p2 = __expf(sf[f][2] - mn1);
            float p3 = __expf(sf[f][3] - mn1);
            l0 += p0 + p1;
            l1 += p2 + p3;
            __nv_bfloat16 h0, lo0, h1, lo1, h2, lo2, h3, lo3;
            split_f(p0, h0, lo0); split_f(p1, h1, lo1);
            split_f(p2, h2, lo2); split_f(p3, h3, lo3);
            int ks = f >> 1, o = (f & 1) * 2;
            __nv_bfloat162 hp01(h0, h1), hp23(h2, h3);
            __nv_bfloat162 lp01(lo0, lo1), lp23(lo2, lo3);
            ph[ks][o]     = *(uint32_t*)&hp01;
            ph[ks][o + 1] = *(uint32_t*)&hp23;
            pl[ks][o]     = *(uint32_t*)&lp01;
            pl[ks][o + 1] = *(uint32_t*)&lp23;
        }

        // ---- O += P V (3 passes) ----
        uint32_t vst = kst + 2 * ATB;
#pragma unroll
        for (int ks = 0; ks < 4; ks++) {
#pragma unroll
            for (int nb = 0; nb < 4; nb++) {
                uint32_t vo = (uint32_t)((ks * 16 + a_row) * ARS + nb * 32 + a_cb);
                uint32_t vh4[4], vl4[4];
                ldsm4t(vh4, vst + vo);
                ldsm4t(vl4, vst + ATB + vo);
                mma16816(of[2 * nb],     ph[ks], vh4[0], vh4[1]);
                mma16816(of[2 * nb + 1], ph[ks], vh4[2], vh4[3]);
                mma16816(of[2 * nb],     ph[ks], vl4[0], vl4[1]);
                mma16816(of[2 * nb + 1], ph[ks], vl4[2], vl4[3]);
                mma16816(of[2 * nb],     pl[ks], vh4[0], vh4[1]);
                mma16816(of[2 * nb + 1], pl[ks], vh4[2], vh4[3]);
            }
        }
        __syncthreads();
    }

    // ---- finalize ----
    l0 += __shfl_xor_sync(0xffffffffu, l0, 1);
    l0 += __shfl_xor_sync(0xffffffffu, l0, 2);
    l1 += __shfl_xor_sync(0xffffffffu, l1, 1);
    l1 += __shfl_xor_sync(0xffffffffu, l1, 2);
    float i0 = 1.f / l0, i1 = 1.f / l1;

    int r0g = b * SEQ + q0 + w * 16 + row_in0;
#pragma unroll
    for (int f = 0; f < 8; f++) {
        int col = head * 64 + f * 8 + colb2;
        float v0 = of[f][0] * i0, v1 = of[f][1] * i0;
        float v2 = of[f][2] * i1, v3 = of[f][3] * i1;
        __nv_bfloat16 h0, lo0, h1, lo1, h2, lo2, h3, lo3;
        split_f(v0, h0, lo0); split_f(v1, h1, lo1);
        split_f(v2, h2, lo2); split_f(v3, h3, lo3);
        *(__nv_bfloat162*)(ohi + (size_t)r0g * DM + col)       = __nv_bfloat162(h0, h1);
        *(__nv_bfloat162*)(olo + (size_t)r0g * DM + col)       = __nv_bfloat162(lo0, lo1);
        *(__nv_bfloat162*)(ohi + (size_t)(r0g + 8) * DM + col) = __nv_bfloat162(h2, h3);
        *(__nv_bfloat162*)(olo + (size_t)(r0g + 8) * DM + col) = __nv_bfloat162(lo2, lo3);
    }
}

// ---------------- host ----------------
extern "C" void kernel_launch(void* const* d_in, const int* in_sizes, int n_in,
                              void* d_out, int out_size)
{
    const float* x      = (const float*)d_in[0];
    const float* ln1_w  = (const float*)d_in[1];
    const float* ln1_b  = (const float*)d_in[2];
    const float* ln2_w  = (const float*)d_in[3];
    const float* ln2_b  = (const float*)d_in[4];
    const float* qkv_w  = (const float*)d_in[5];
    const float* o_w    = (const float*)d_in[6];
    const float* ffn_w1 = (const float*)d_in[7];
    const float* ffn_b1 = (const float*)d_in[8];
    const float* ffn_w2 = (const float*)d_in[9];
    const float* ffn_b2 = (const float*)d_in[10];
    float* out = (float*)d_out;

    float* x1;
    cudaGetSymbolAddress((void**)&x1, g_x1);
    __nv_bfloat16 *qw_h, *qw_l, *ow_h, *ow_l, *w1_h, *w1_l, *w2_h, *w2_l;
    __nv_bfloat16 *h_h, *h_l, *qkv_h, *qkv_l, *at_h, *at_l, *h2_h, *h2_l, *f1_h, *f1_l;
    cudaGetSymbolAddress((void**)&qw_h, g_qkvw_hi); cudaGetSymbolAddress((void**)&qw_l, g_qkvw_lo);
    cudaGetSymbolAddress((void**)&ow_h, g_ow_hi);   cudaGetSymbolAddress((void**)&ow_l, g_ow_lo);
    cudaGetSymbolAddress((void**)&w1_h, g_w1_hi);   cudaGetSymbolAddress((void**)&w1_l, g_w1_lo);
    cudaGetSymbolAddress((void**)&w2_h, g_w2_hi);   cudaGetSymbolAddress((void**)&w2_l, g_w2_lo);
    cudaGetSymbolAddress((void**)&h_h,  g_h_hi);    cudaGetSymbolAddress((void**)&h_l,  g_h_lo);
    cudaGetSymbolAddress((void**)&qkv_h, g_qkv_hi); cudaGetSymbolAddress((void**)&qkv_l, g_qkv_lo);
    cudaGetSymbolAddress((void**)&at_h, g_at_hi);   cudaGetSymbolAddress((void**)&at_l, g_at_lo);
    cudaGetSymbolAddress((void**)&h2_h, g_h2_hi);   cudaGetSymbolAddress((void**)&h2_l, g_h2_lo);
    cudaGetSymbolAddress((void**)&f1_h, g_f1_hi);   cudaGetSymbolAddress((void**)&f1_l, g_f1_lo);

    cudaFuncSetAttribute(gemm_mma, cudaFuncAttributeMaxDynamicSharedMemorySize, SMEM_TOT);
    cudaFuncSetAttribute(attn_mma, cudaFuncAttributeMaxDynamicSharedMemorySize, ASM_TOT);

    auto splitN = [&](const float* src, __nv_bfloat16* hi, __nv_bfloat16* lo, int n) {
        split4<<<n / 1024, 256>>>((const float4*)src, (__nv_bfloat162*)hi, (__nv_bfloat162*)lo, n / 4);
    };

    splitN(qkv_w,  qw_h, qw_l, 3 * DM * DM);
    splitN(o_w,    ow_h, ow_l, DM * DM);
    splitN(ffn_w1, w1_h, w1_l, 4 * DM * DM);
    splitN(ffn_w2, w2_h, w2_l, 4 * DM * DM);

    // h = LN1(x) -> hi/lo
    ln_split<<<TOK, 256>>>(x, ln1_w, ln1_b, h_h, h_l);
    // qkv = h @ qkv_w^T -> hi/lo
    gemm_mma<<<dim3(3 * DM / 128, TOK / 128), 256, SMEM_TOT>>>(h_h, h_l, qw_h, qw_l,
        nullptr, nullptr, nullptr, qkv_h, qkv_l, 3 * DM, DM, 0);
    // attention -> hi/lo
    attn_mma<<<dim3(SEQ / 64, NHEAD, 2), 128, ASM_TOT>>>(qkv_h, qkv_l, at_h, at_l);
    // x1 = x + attn @ o_w^T (fp32)
    gemm_mma<<<dim3(DM / 128, TOK / 128), 256, SMEM_TOT>>>(at_h, at_l, ow_h, ow_l,
        nullptr, x, x1, nullptr, nullptr, DM, DM, 0);
    // h2 = LN2(x1) -> hi/lo
    ln_split<<<TOK, 256>>>(x1, ln2_w, ln2_b, h2_h, h2_l);
    // ff1 = gelu(h2 @ ffn_w1^T + b1) -> hi/lo
    gemm_mma<<<dim3(4 * DM / 128, TOK / 128), 256, SMEM_TOT>>>(h2_h, h2_l, w1_h, w1_l,
        ffn_b1, nullptr, nullptr, f1_h, f1_l, 4 * DM, DM, 1);
    // out = x1 + ff1 @ ffn_w2^T + b2 (fp32)
    gemm_mma<<<dim3(DM / 128, TOK / 128), 256, SMEM_TOT>>>(f1_h, f1_l, w2_h, w2_l,
        ffn_b2, x1, out, nullptr, nullptr, DM, 4 * DM, 0);
}

// round 12
// speedup vs baseline: 1.0023x; 1.0023x over previous
#include <cuda_runtime.h>
#include <cuda_bf16.h>
#include <math.h>
#include <stdint.h>

#define TOK 4096      // B*N = 2*2048
#define DM  1024
#define SEQ 2048
#define NHEAD 16

// ---------------- scratch (no cudaMalloc allowed) ----------------
__device__ float g_x1  [TOK * DM];

__device__ __nv_bfloat16 g_qkvw_hi[3 * DM * DM], g_qkvw_lo[3 * DM * DM];
__device__ __nv_bfloat16 g_ow_hi  [DM * DM],     g_ow_lo  [DM * DM];
__device__ __nv_bfloat16 g_w1_hi  [4 * DM * DM], g_w1_lo  [4 * DM * DM];
__device__ __nv_bfloat16 g_w2_hi  [4 * DM * DM], g_w2_lo  [4 * DM * DM];
__device__ __nv_bfloat16 g_h_hi   [TOK * DM],    g_h_lo   [TOK * DM];
__device__ __nv_bfloat16 g_qkv_hi [TOK * 3 * DM],g_qkv_lo [TOK * 3 * DM];
__device__ __nv_bfloat16 g_at_hi  [TOK * DM],    g_at_lo  [TOK * DM];
__device__ __nv_bfloat16 g_h2_hi  [TOK * DM],    g_h2_lo  [TOK * DM];
__device__ __nv_bfloat16 g_f1_hi  [TOK * 4 * DM],g_f1_lo  [TOK * 4 * DM];

// ---------------- helpers ----------------
__device__ __forceinline__ uint32_t smem_u32(const void* p) {
    uint32_t a;
    asm("{ .reg .u64 t; cvta.to.shared.u64 t, %1; cvt.u32.u64 %0, t; }" : "=r"(a) : "l"(p));
    return a;
}
#define CP_ASYNC16(sa, ga) \
    asm volatile("cp.async.cg.shared.global [%0], [%1], 16;" :: "r"(sa), "l"(ga))
#define CP_COMMIT() asm volatile("cp.async.commit_group;" ::: "memory")
#define CP_WAIT1()  asm volatile("cp.async.wait_group 1;" ::: "memory")

__device__ __forceinline__ void ldsm4(uint32_t* r, uint32_t addr) {
    asm volatile("ldmatrix.sync.aligned.m8n8.x4.shared.b16 {%0,%1,%2,%3}, [%4];"
                 : "=r"(r[0]), "=r"(r[1]), "=r"(r[2]), "=r"(r[3]) : "r"(addr));
}
__device__ __forceinline__ void ldsm4t(uint32_t* r, uint32_t addr) {
    asm volatile("ldmatrix.sync.aligned.m8n8.x4.trans.shared.b16 {%0,%1,%2,%3}, [%4];"
                 : "=r"(r[0]), "=r"(r[1]), "=r"(r[2]), "=r"(r[3]) : "r"(addr));
}
__device__ __forceinline__ void mma16816(float* d, const uint32_t* a, uint32_t b0, uint32_t b1) {
    asm volatile("mma.sync.aligned.m16n8k16.row.col.f32.bf16.bf16.f32 "
                 "{%0,%1,%2,%3}, {%4,%5,%6,%7}, {%8,%9}, {%0,%1,%2,%3};"
                 : "+f"(d[0]), "+f"(d[1]), "+f"(d[2]), "+f"(d[3])
                 : "r"(a[0]), "r"(a[1]), "r"(a[2]), "r"(a[3]), "r"(b0), "r"(b1));
}
__device__ __forceinline__ void split_f(float v, __nv_bfloat16& h, __nv_bfloat16& l) {
    h = __float2bfloat16(v);
    l = __float2bfloat16(v - __bfloat162float(h));
}

// ---------------- fp32 -> bf16 hi/lo split (weights only) ----------------
__global__ __launch_bounds__(256) void split4(const float4* __restrict__ in,
                                              __nv_bfloat162* __restrict__ hi,
                                              __nv_bfloat162* __restrict__ lo, int n4)
{
    int i = blockIdx.x * 256 + threadIdx.x;
    if (i >= n4) return;
    float4 x = in[i];
    __nv_bfloat16 h0, l0, h1, l1, h2, l2, h3, l3;
    split_f(x.x, h0, l0); split_f(x.y, h1, l1);
    split_f(x.z, h2, l2); split_f(x.w, h3, l3);
    hi[2 * i]     = __nv_bfloat162(h0, h1);
    hi[2 * i + 1] = __nv_bfloat162(h2, h3);
    lo[2 * i]     = __nv_bfloat162(l0, l1);
    lo[2 * i + 1] = __nv_bfloat162(l2, l3);
}

// ---------------- LayerNorm -> bf16 hi/lo ----------------
__global__ __launch_bounds__(256) void ln_split(const float* __restrict__ x,
                                                const float* __restrict__ w,
                                                const float* __restrict__ b,
                                                __nv_bfloat16* __restrict__ ohi,
                                                __nv_bfloat16* __restrict__ olo)
{
    int row = blockIdx.x;
    const float* xr = x + (size_t)row * DM;
    float v[4];
    float sum = 0.f, sq = 0.f;
#pragma unroll
    for (int k = 0; k < 4; k++) {
        v[k] = xr[threadIdx.x + 256 * k];
        sum += v[k];
        sq  += v[k] * v[k];
    }
#pragma unroll
    for (int o = 16; o > 0; o >>= 1) {
        sum += __shfl_xor_sync(0xffffffffu, sum, o);
        sq  += __shfl_xor_sync(0xffffffffu, sq, o);
    }
    __shared__ float ssum[8], ssq[8], s_mu, s_rinv;
    int wid = threadIdx.x >> 5, lid = threadIdx.x & 31;
    if (lid == 0) { ssum[wid] = sum; ssq[wid] = sq; }
    __syncthreads();
    if (threadIdx.x == 0) {
        float ts = 0.f, tq = 0.f;
#pragma unroll
        for (int i = 0; i < 8; i++) { ts += ssum[i]; tq += ssq[i]; }
        float mu  = ts * (1.0f / DM);
        float var = tq * (1.0f / DM) - mu * mu;
        s_mu = mu; s_rinv = rsqrtf(var + 1e-5f);
    }
    __syncthreads();
    float mu = s_mu, rinv = s_rinv;
#pragma unroll
    for (int k = 0; k < 4; k++) {
        int c = threadIdx.x + 256 * k;
        float val = (v[k] - mu) * rinv * w[c] + b[c];
        __nv_bfloat16 h, l;
        split_f(val, h, l);
        ohi[(size_t)row * DM + c] = h;
        olo[(size_t)row * DM + c] = l;
    }
}

// ---------------- mma.sync GEMM: C[M,N] = A[M,K] @ W[N,K]^T ----------------
#define BK 32
#define MAT_B (128 * 40 * 2)           // 10240 bytes per matrix tile (80B rows)
#define STG_B (4 * MAT_B)
#define SMEM_TOT (2 * STG_B)

__global__ __launch_bounds__(256, 1) void gemm_mma(
    const __nv_bfloat16* __restrict__ Ah, const __nv_bfloat16* __restrict__ Al,
    const __nv_bfloat16* __restrict__ Wh, const __nv_bfloat16* __restrict__ Wl,
    const float* __restrict__ bias, const float* __restrict__ res,
    float* __restrict__ C,
    __nv_bfloat16* __restrict__ Chi, __nv_bfloat16* __restrict__ Clo,
    int N, int K, int do_gelu)
{
    extern __shared__ char smem[];
    uint32_t sbase = smem_u32(smem);
    int t = threadIdx.x;
    int w = t >> 5, lane = t & 31;
    int warp_m = w & 1, warp_n = w >> 1;
    int lr = lane & 15, lh = lane >> 4;

    int row0 = blockIdx.y * 128;
    int col0 = blockIdx.x * 128;
    const __nv_bfloat16* srcs[4] = {
        Ah + (size_t)row0 * K, Al + (size_t)row0 * K,
        Wh + (size_t)col0 * K, Wl + (size_t)col0 * K };

    float acc[4][4][4];
#pragma unroll
    for (int i = 0; i < 4; i++)
#pragma unroll
        for (int j = 0; j < 4; j++)
#pragma unroll
            for (int q = 0; q < 4; q++) acc[i][j][q] = 0.f;

    int niter = K / BK;

    {
        uint32_t sst = sbase;
#pragma unroll
        for (int c8 = 0; c8 < 8; c8++) {
            int c = c8 * 256 + t;
            int mat = c >> 9, rem = c & 511, r = rem >> 2, q = rem & 3;
            CP_ASYNC16(sst + mat * MAT_B + r * 80 + q * 16,
                       srcs[mat] + (size_t)r * K + q * 8);
        }
        CP_COMMIT();
    }

    for (int it = 0; it < niter; it++) {
        if (it + 1 < niter) {
            uint32_t sst = sbase + ((it + 1) & 1) * STG_B;
            int k0 = (it + 1) * BK;
#pragma unroll
            for (int c8 = 0; c8 < 8; c8++) {
                int c = c8 * 256 + t;
                int mat = c >> 9, rem = c & 511, r = rem >> 2, q = rem & 3;
                CP_ASYNC16(sst + mat * MAT_B + r * 80 + q * 16,
                           srcs[mat] + (size_t)r * K + k0 + q * 8);
            }
        }
        CP_COMMIT();
        CP_WAIT1();
        __syncthreads();

        uint32_t sst = sbase + (it & 1) * STG_B;
#pragma unroll
        for (int ks = 0; ks < 2; ks++) {
            uint32_t coff = ks * 32 + lh * 16;
            uint32_t ah[4][4], al[4][4], bh[2][4], bl[2][4];
#pragma unroll
            for (int mt = 0; mt < 4; mt++) {
                uint32_t rofs = (warp_m * 64 + mt * 16 + lr) * 80 + coff;
                ldsm4(ah[mt], sst + rofs);
                ldsm4(al[mt], sst + MAT_B + rofs);
            }
#pragma unroll
            for (int p = 0; p < 2; p++) {
                uint32_t rofs = (warp_n * 32 + p * 16 + lr) * 80 + coff;
                ldsm4(bh[p], sst + 2 * MAT_B + rofs);
                ldsm4(bl[p], sst + 3 * MAT_B + rofs);
            }
#pragma unroll
            for (int mt = 0; mt < 4; mt++)
#pragma unroll
                for (int nt = 0; nt < 4; nt++) {
                    int p = nt >> 1, o = nt & 1;
                    mma16816(acc[mt][nt], ah[mt], bh[p][o], bh[p][o + 2]);
                }
#pragma unroll
            for (int mt = 0; mt < 4; mt++)
#pragma unroll
                for (int nt = 0; nt < 4; nt++) {
                    int p = nt >> 1, o = nt & 1;
                    mma16816(acc[mt][nt], ah[mt], bl[p][o], bl[p][o + 2]);
                }
#pragma unroll
            for (int mt = 0; mt < 4; mt++)
#pragma unroll
                for (int nt = 0; nt < 4; nt++) {
                    int p = nt >> 1, o = nt & 1;
                    mma16816(acc[mt][nt], al[mt], bh[p][o], bh[p][o + 2]);
                }
        }
        __syncthreads();
    }

    int g = lane >> 2, tig = lane & 3;
#pragma unroll
    for (int mt = 0; mt < 4; mt++) {
#pragma unroll
        for (int nt = 0; nt < 4; nt++) {
            int col = col0 + warp_n * 32 + nt * 8 + tig * 2;
            float b0 = 0.f, b1 = 0.f;
            if (bias) { b0 = bias[col]; b1 = bias[col + 1]; }
#pragma unroll
            for (int hrow = 0; hrow < 2; hrow++) {
                int row = row0 + warp_m * 64 + mt * 16 + g + hrow * 8;
                float vx = acc[mt][nt][hrow * 2]     + b0;
                float vy = acc[mt][nt][hrow * 2 + 1] + b1;
                if (do_gelu) {
                    vx = 0.5f * vx * (1.f + erff(vx * 0.70710678f));
                    vy = 0.5f * vy * (1.f + erff(vy * 0.70710678f));
                }
                if (res) {
                    vx += res[(size_t)row * N + col];
                    vy += res[(size_t)row * N + col + 1];
                }
                if (C) {
                    *(float2*)(C + (size_t)row * N + col) = make_float2(vx, vy);
                }
                if (Chi) {
                    __nv_bfloat16 hx, lx, hy, ly;
                    split_f(vx, hx, lx); split_f(vy, hy, ly);
                    *(__nv_bfloat162*)(Chi + (size_t)row * N + col) = __nv_bfloat162(hx, hy);
                    *(__nv_bfloat162*)(Clo + (size_t)row * N + col) = __nv_bfloat162(lx, ly);
                }
            }
        }
    }
}

// ---------------- tensor-core causal flash attention ----------------
// BM=64 q-rows/CTA, 4 warps x 16 rows; kv tiles of 64 double-buffered.
// Full split precision: S = Qh*Kh + Qh*Kl + Ql*Kh ; O += Ph*Vh + Ph*Vl + Pl*Vh
#define ARS   144                     // smem row bytes (64*2 + 16 pad)
#define ATB   (64 * ARS)              // 9216 per matrix
#define AQ_B  (2 * ATB)               // Qh, Ql
#define ASTG  (4 * ATB)               // Kh, Kl, Vh, Vl
#define ASM_TOT (AQ_B + 2 * ASTG)     // 92160

__global__ __launch_bounds__(128) void attn_mma(
    const __nv_bfloat16* __restrict__ qkvh, const __nv_bfloat16* __restrict__ qkvl,
    __nv_bfloat16* __restrict__ ohi, __nv_bfloat16* __restrict__ olo)
{
    extern __shared__ char smem[];
    uint32_t sb = smem_u32(smem);
    int t = threadIdx.x, w = t >> 5, lane = t & 31;
    int qt = blockIdx.x, head = blockIdx.y, b = blockIdx.z;
    int q0 = qt * 64;

    // ldmatrix x4 address patterns (relative row/col within a 16x16 block)
    int a_row = (lane & 7) + ((lane & 8) ? 8 : 0);    // a-style / V-trans
    int a_cb  = (lane & 16) ? 16 : 0;
    int b_row = (lane & 7) + ((lane & 16) ? 8 : 0);   // K b-style (no trans)
    int b_cb  = (lane & 8) ? 16 : 0;

    // ---- load Q (hi/lo) ----
#pragma unroll
    for (int i = 0; i < 8; i++) {
        int c = i * 128 + t;
        int mat = c >> 9, rem = c & 511, r = rem >> 3, c16 = rem & 7;
        const __nv_bfloat16* src = (mat ? qkvl : qkvh) +
            ((size_t)(b * SEQ + q0 + r) * (3 * DM) + head * 64 + c16 * 8);
        CP_ASYNC16(sb + mat * ATB + r * ARS + c16 * 16, src);
    }
    CP_COMMIT();

    // ---- prefetch kv tile 0 ----
    {
        uint32_t sst = sb + AQ_B;
#pragma unroll
        for (int i = 0; i < 16; i++) {
            int c = i * 128 + t;
            int mat = c >> 9, rem = c & 511, r = rem >> 3, c16 = rem & 7;
            const __nv_bfloat16* base = (mat & 1) ? qkvl : qkvh;
            int off = (mat >> 1) ? 2 * DM : DM;
            const __nv_bfloat16* src = base +
                ((size_t)(b * SEQ + r) * (3 * DM) + off + head * 64 + c16 * 8);
            CP_ASYNC16(sst + mat * ATB + r * ARS + c16 * 16, src);
        }
        CP_COMMIT();
    }

    uint32_t qa_h[4][4], qa_l[4][4];
    float of[8][4];
#pragma unroll
    for (int f = 0; f < 8; f++)
#pragma unroll
        for (int q = 0; q < 4; q++) of[f][q] = 0.f;
    float m0 = -1e30f, m1 = -1e30f, l0 = 0.f, l1 = 0.f;

    int row_in0 = (lane >> 2);          // 0..7
    int colb2   = 2 * (lane & 3);       // 0,2,4,6

    for (int kt = 0; kt <= qt; kt++) {
        // prefetch next
        if (kt < qt) {
            uint32_t sst = sb + AQ_B + ((kt + 1) & 1) * ASTG;
            int k0n = (kt + 1) * 64;
#pragma unroll
            for (int i = 0; i < 16; i++) {
                int c = i * 128 + t;
                int mat = c >> 9, rem = c & 511, r = rem >> 3, c16 = rem & 7;
                const __nv_bfloat16* base = (mat & 1) ? qkvl : qkvh;
                int off = (mat >> 1) ? 2 * DM : DM;
                const __nv_bfloat16* src = base +
                    ((size_t)(b * SEQ + k0n + r) * (3 * DM) + off + head * 64 + c16 * 8);
                CP_ASYNC16(sst + mat * ATB + r * ARS + c16 * 16, src);
            }
        }
        CP_COMMIT();
        CP_WAIT1();
        __syncthreads();

        if (kt == 0) {
            // load Q fragments once
#pragma unroll
            for (int ks = 0; ks < 4; ks++) {
                uint32_t ao = (uint32_t)((w * 16 + a_row) * ARS + ks * 32 + a_cb);
                ldsm4(qa_h[ks], sb + ao);
                ldsm4(qa_l[ks], sb + ATB + ao);
            }
        }

        uint32_t kst = sb + AQ_B + (kt & 1) * ASTG;

        // ---- S = Q K^T (3 passes) ----
        float sf[8][4];
#pragma unroll
        for (int f = 0; f < 8; f++)
#pragma unroll
            for (int q = 0; q < 4; q++) sf[f][q] = 0.f;

#pragma unroll
        for (int ks = 0; ks < 4; ks++) {
#pragma unroll
            for (int nb = 0; nb < 4; nb++) {
                uint32_t ko = (uint32_t)((nb * 16 + b_row) * ARS + ks * 32 + b_cb);
                uint32_t kh4[4], kl4[4];
                ldsm4(kh4, kst + ko);
                ldsm4(kl4, kst + ATB + ko);
                mma16816(sf[2 * nb],     qa_h[ks], kh4[0], kh4[1]);
                mma16816(sf[2 * nb + 1], qa_h[ks], kh4[2], kh4[3]);
                mma16816(sf[2 * nb],     qa_h[ks], kl4[0], kl4[1]);
                mma16816(sf[2 * nb + 1], qa_h[ks], kl4[2], kl4[3]);
                mma16816(sf[2 * nb],     qa_l[ks], kh4[0], kh4[1]);
                mma16816(sf[2 * nb + 1], qa_l[ks], kh4[2], kh4[3]);
            }
        }

        // ---- scale + causal mask ----
        int r0 = q0 + w * 16 + row_in0;
        int r1 = r0 + 8;
        int k0 = kt * 64;
#pragma unroll
        for (int f = 0; f < 8; f++) {
#pragma unroll
            for (int q = 0; q < 4; q++) sf[f][q] *= 0.125f;
            if (kt == qt) {
                int c0 = k0 + f * 8 + colb2;
                if (c0 > r0)     sf[f][0] = -1e30f;
                if (c0 + 1 > r0) sf[f][1] = -1e30f;
                if (c0 > r1)     sf[f][2] = -1e30f;
                if (c0 + 1 > r1) sf[f][3] = -1e30f;
            }
        }

        // ---- online softmax ----
        float mx0 = -1e30f, mx1 = -1e30f;
#pragma unroll
        for (int f = 0; f < 8; f++) {
            mx0 = fmaxf(mx0, fmaxf(sf[f][0], sf[f][1]));
            mx1 = fmaxf(mx1, fmaxf(sf[f][2], sf[f][3]));
        }
        mx0 = fmaxf(mx0, __shfl_xor_sync(0xffffffffu, mx0, 1));
        mx0 = fmaxf(mx0, __shfl_xor_sync(0xffffffffu, mx0, 2));
        mx1 = fmaxf(mx1, __shfl_xor_sync(0xffffffffu, mx1, 1));
        mx1 = fmaxf(mx1, __shfl_xor_sync(0xffffffffu, mx1, 2));
        float mn0 = fmaxf(m0, mx0), mn1 = fmaxf(m1, mx1);
        float cr0 = __expf(m0 - mn0), cr1 = __expf(m1 - mn1);
        m0 = mn0; m1 = mn1;
        l0 *= cr0; l1 *= cr1;
#pragma unroll
        for (int f = 0; f < 8; f++) {
            of[f][0] *= cr0; of[f][1] *= cr0;
            of[f][2] *= cr1; of[f][3] *= cr1;
        }

        uint32_t ph[4][4], pl[4][4];
#pragma unroll
        for (int f = 0; f < 8; f++) {
            float p0 = __expf(sf[f][0] - mn0);
            float p1 = __expf(sf[f][1] - mn0);
            float p2 = __expf(sf[f][2] - mn1);
            float p3 = __expf(sf[f][3] - mn1);
            l0 += p0 + p1;
            l1 += p2 + p3;
            __nv_bfloat16 h0, lo0, h1, lo1, h2, lo2, h3, lo3;
            split_f(p0, h0, lo0); split_f(p1, h1, lo1);
            split_f(p2, h2, lo2); split_f(p3, h3, lo3);
            int ks = f >> 1, o = (f & 1) * 2;
            __nv_bfloat162 hp01(h0, h1), hp23(h2, h3);
            __nv_bfloat162 lp01(lo0, lo1), lp23(lo2, lo3);
            ph[ks][o]     = *(uint32_t*)&hp01;
            ph[ks][o + 1] = *(uint32_t*)&hp23;
            pl[ks][o]     = *(uint32_t*)&lp01;
            pl[ks][o + 1] = *(uint32_t*)&lp23;
        }

        // ---- O += P V (3 passes) ----
        uint32_t vst = kst + 2 * ATB;
#pragma unroll
        for (int ks = 0; ks < 4; ks++) {
#pragma unroll
            for (int nb = 0; nb < 4; nb++) {
                uint32_t vo = (uint32_t)((ks * 16 + a_row) * ARS + nb * 32 + a_cb);
                uint32_t vh4[4], vl4[4];
                ldsm4t(vh4, vst + vo);
                ldsm4t(vl4, vst + ATB + vo);
                mma16816(of[2 * nb],     ph[ks], vh4[0], vh4[1]);
                mma16816(of[2 * nb + 1], ph[ks], vh4[2], vh4[3]);
                mma16816(of[2 * nb],     ph[ks], vl4[0], vl4[1]);
                mma16816(of[2 * nb + 1], ph[ks], vl4[2], vl4[3]);
                mma16816(of[2 * nb],     pl[ks], vh4[0], vh4[1]);
                mma16816(of[2 * nb + 1], pl[ks], vh4[2], vh4[3]);
            }
        }
        __syncthreads();
    }

    // ---- finalize ----
    l0 += __shfl_xor_sync(0xffffffffu, l0, 1);
    l0 += __shfl_xor_sync(0xffffffffu, l0, 2);
    l1 += __shfl_xor_sync(0xffffffffu, l1, 1);
    l1 += __shfl_xor_sync(0xffffffffu, l1, 2);
    float i0 = 1.f / l0, i1 = 1.f / l1;

    int r0g = b * SEQ + q0 + w * 16 + row_in0;
#pragma unroll
    for (int f = 0; f < 8; f++) {
        int col = head * 64 + f * 8 + colb2;
        float v0 = of[f][0] * i0, v1 = of[f][1] * i0;
        float v2 = of[f][2] * i1, v3 = of[f][3] * i1;
        __nv_bfloat16 h0, lo0, h1, lo1, h2, lo2, h3, lo3;
        split_f(v0, h0, lo0); split_f(v1, h1, lo1);
        split_f(v2, h2, lo2); split_f(v3, h3, lo3);
        *(__nv_bfloat162*)(ohi + (size_t)r0g * DM + col)       = __nv_bfloat162(h0, h1);
        *(__nv_bfloat162*)(olo + (size_t)r0g * DM + col)       = __nv_bfloat162(lo0, lo1);
        *(__nv_bfloat162*)(ohi + (size_t)(r0g + 8) * DM + col) = __nv_bfloat162(h2, h3);
        *(__nv_bfloat162*)(olo + (size_t)(r0g + 8) * DM + col) = __nv_bfloat162(lo2, lo3);
    }
}

// ---------------- host ----------------
extern "C" void kernel_launch(void* const* d_in, const int* in_sizes, int n_in,
                              void* d_out, int out_size)
{
    const float* x      = (const float*)d_in[0];
    const float* ln1_w  = (const float*)d_in[1];
    const float* ln1_b  = (const float*)d_in[2];
    const float* ln2_w  = (const float*)d_in[3];
    const float* ln2_b  = (const float*)d_in[4];
    const float* qkv_w  = (const float*)d_in[5];
    const float* o_w    = (const float*)d_in[6];
    const float* ffn_w1 = (const float*)d_in[7];
    const float* ffn_b1 = (const float*)d_in[8];
    const float* ffn_w2 = (const float*)d_in[9];
    const float* ffn_b2 = (const float*)d_in[10];
    float* out = (float*)d_out;

    float* x1;
    cudaGetSymbolAddress((void**)&x1, g_x1);
    __nv_bfloat16 *qw_h, *qw_l, *ow_h, *ow_l, *w1_h, *w1_l, *w2_h, *w2_l;
    __nv_bfloat16 *h_h, *h_l, *qkv_h, *qkv_l, *at_h, *at_l, *h2_h, *h2_l, *f1_h, *f1_l;
    cudaGetSymbolAddress((void**)&qw_h, g_qkvw_hi); cudaGetSymbolAddress((void**)&qw_l, g_qkvw_lo);
    cudaGetSymbolAddress((void**)&ow_h, g_ow_hi);   cudaGetSymbolAddress((void**)&ow_l, g_ow_lo);
    cudaGetSymbolAddress((void**)&w1_h, g_w1_hi);   cudaGetSymbolAddress((void**)&w1_l, g_w1_lo);
    cudaGetSymbolAddress((void**)&w2_h, g_w2_hi);   cudaGetSymbolAddress((void**)&w2_l, g_w2_lo);
    cudaGetSymbolAddress((void**)&h_h,  g_h_hi);    cudaGetSymbolAddress((void**)&h_l,  g_h_lo);
    cudaGetSymbolAddress((void**)&qkv_h, g_qkv_hi); cudaGetSymbolAddress((void**)&qkv_l, g_qkv_lo);
    cudaGetSymbolAddress((void**)&at_h, g_at_hi);   cudaGetSymbolAddress((void**)&at_l, g_at_lo);
    cudaGetSymbolAddress((void**)&h2_h, g_h2_hi);   cudaGetSymbolAddress((void**)&h2_l, g_h2_lo);
    cudaGetSymbolAddress((void**)&f1_h, g_f1_hi);   cudaGetSymbolAddress((void**)&f1_l, g_f1_lo);

    cudaFuncSetAttribute(gemm_mma, cudaFuncAttributeMaxDynamicSharedMemorySize, SMEM_TOT);
    cudaFuncSetAttribute(attn_mma, cudaFuncAttributeMaxDynamicSharedMemorySize, ASM_TOT);

    auto splitN = [&](const float* src, __nv_bfloat16* hi, __nv_bfloat16* lo, int n) {
        split4<<<n / 1024, 256>>>((const float4*)src, (__nv_bfloat162*)hi, (__nv_bfloat162*)lo, n / 4);
    };

    splitN(qkv_w,  qw_h, qw_l, 3 * DM * DM);
    splitN(o_w,    ow_h, ow_l, DM * DM);
    splitN(ffn_w1, w1_h, w1_l, 4 * DM * DM);
    splitN(ffn_w2, w2_h, w2_l, 4 * DM * DM);

    // h = LN1(x) -> hi/lo
    ln_split<<<TOK, 256>>>(x, ln1_w, ln1_b, h_h, h_l);
    // qkv = h @ qkv_w^T -> hi/lo
    gemm_mma<<<dim3(3 * DM / 128, TOK / 128), 256, SMEM_TOT>>>(h_h, h_l, qw_h, qw_l,
        nullptr, nullptr, nullptr, qkv_h, qkv_l, 3 * DM, DM, 0);
    // attention -> hi/lo
    attn_mma<<<dim3(SEQ / 64, NHEAD, 2), 128, ASM_TOT>>>(qkv_h, qkv_l, at_h, at_l);
    // x1 = x + attn @ o_w^T (fp32)
    gemm_mma<<<dim3(DM / 128, TOK / 128), 256, SMEM_TOT>>>(at_h, at_l, ow_h, ow_l,
        nullptr, x, x1, nullptr, nullptr, DM, DM, 0);
    // h2 = LN2(x1) -> hi/lo
    ln_split<<<TOK, 256>>>(x1, ln2_w, ln2_b, h2_h, h2_l);
    // ff1 = gelu(h2 @ ffn_w1^T + b1) -> hi/lo
    gemm_mma<<<dim3(4 * DM / 128, TOK / 128), 256, SMEM_TOT>>>(h2_h, h2_l, w1_h, w1_l,
        ffn_b1, nullptr, nullptr, f1_h, f1_l, 4 * DM, DM, 1);
    // out = x1 + ff1 @ ffn_w2^T + b2 (fp32)
    gemm_mma<<<dim3(DM / 128, TOK / 128), 256, SMEM_TOT>>>(f1_h, f1_l, w2_h, w2_l,
        ffn_b2, x1, out, nullptr, nullptr, DM, 4 * DM, 0);
}

// round 13
// speedup vs baseline: 1.0027x; 1.0005x over previous
#include <cuda_runtime.h>
#include <cuda_bf16.h>
#include <math.h>
#include <stdint.h>

#define TOK 4096      // B*N = 2*2048
#define DM  1024
#define SEQ 2048
#define NHEAD 16

// ---------------- scratch (no cudaMalloc allowed) ----------------
__device__ float g_x1  [TOK * DM];

__device__ __nv_bfloat16 g_qkvw_hi[3 * DM * DM], g_qkvw_lo[3 * DM * DM];
__device__ __nv_bfloat16 g_ow_hi  [DM * DM],     g_ow_lo  [DM * DM];
__device__ __nv_bfloat16 g_w1_hi  [4 * DM * DM], g_w1_lo  [4 * DM * DM];
__device__ __nv_bfloat16 g_w2_hi  [4 * DM * DM], g_w2_lo  [4 * DM * DM];
__device__ __nv_bfloat16 g_h_hi   [TOK * DM],    g_h_lo   [TOK * DM];
__device__ __nv_bfloat16 g_qkv_hi [TOK * 3 * DM],g_qkv_lo [TOK * 3 * DM];
__device__ __nv_bfloat16 g_at_hi  [TOK * DM],    g_at_lo  [TOK * DM];
__device__ __nv_bfloat16 g_h2_hi  [TOK * DM],    g_h2_lo  [TOK * DM];
__device__ __nv_bfloat16 g_f1_hi  [TOK * 4 * DM],g_f1_lo  [TOK * 4 * DM];

// ---------------- helpers ----------------
__device__ __forceinline__ uint32_t smem_u32(const void* p) {
    uint32_t a;
    asm("{ .reg .u64 t; cvta.to.shared.u64 t, %1; cvt.u32.u64 %0, t; }" : "=r"(a) : "l"(p));
    return a;
}
#define CP_ASYNC16(sa, ga) \
    asm volatile("cp.async.cg.shared.global [%0], [%1], 16;" :: "r"(sa), "l"(ga))
#define CP_COMMIT() asm volatile("cp.async.commit_group;" ::: "memory")
#define CP_WAIT1()  asm volatile("cp.async.wait_group 1;" ::: "memory")

__device__ __forceinline__ void ldsm4(uint32_t* r, uint32_t addr) {
    asm volatile("ldmatrix.sync.aligned.m8n8.x4.shared.b16 {%0,%1,%2,%3}, [%4];"
                 : "=r"(r[0]), "=r"(r[1]), "=r"(r[2]), "=r"(r[3]) : "r"(addr));
}
__device__ __forceinline__ void ldsm4t(uint32_t* r, uint32_t addr) {
    asm volatile("ldmatrix.sync.aligned.m8n8.x4.trans.shared.b16 {%0,%1,%2,%3}, [%4];"
                 : "=r"(r[0]), "=r"(r[1]), "=r"(r[2]), "=r"(r[3]) : "r"(addr));
}
__device__ __forceinline__ void mma16816(float* d, const uint32_t* a, uint32_t b0, uint32_t b1) {
    asm volatile("mma.sync.aligned.m16n8k16.row.col.f32.bf16.bf16.f32 "
                 "{%0,%1,%2,%3}, {%4,%5,%6,%7}, {%8,%9}, {%0,%1,%2,%3};"
                 : "+f"(d[0]), "+f"(d[1]), "+f"(d[2]), "+f"(d[3])
                 : "r"(a[0]), "r"(a[1]), "r"(a[2]), "r"(a[3]), "r"(b0), "r"(b1));
}
__device__ __forceinline__ void split_f(float v, __nv_bfloat16& h, __nv_bfloat16& l) {
    h = __float2bfloat16(v);
    l = __float2bfloat16(v - __bfloat162float(h));
}

// ---------------- fp32 -> bf16 hi/lo split (weights only) ----------------
__global__ __launch_bounds__(256) void split4(const float4* __restrict__ in,
                                              __nv_bfloat162* __restrict__ hi,
                                              __nv_bfloat162* __restrict__ lo, int n4)
{
    int i = blockIdx.x * 256 + threadIdx.x;
    if (i >= n4) return;
    float4 x = in[i];
    __nv_bfloat16 h0, l0, h1, l1, h2, l2, h3, l3;
    split_f(x.x, h0, l0); split_f(x.y, h1, l1);
    split_f(x.z, h2, l2); split_f(x.w, h3, l3);
    hi[2 * i]     = __nv_bfloat162(h0, h1);
    hi[2 * i + 1] = __nv_bfloat162(h2, h3);
    lo[2 * i]     = __nv_bfloat162(l0, l1);
    lo[2 * i + 1] = __nv_bfloat162(l2, l3);
}

// ---------------- LayerNorm -> bf16 hi/lo ----------------
__global__ __launch_bounds__(256) void ln_split(const float* __restrict__ x,
                                                const float* __restrict__ w,
                                                const float* __restrict__ b,
                                                __nv_bfloat16* __restrict__ ohi,
                                                __nv_bfloat16* __restrict__ olo)
{
    int row = blockIdx.x;
    const float* xr = x + (size_t)row * DM;
    float v[4];
    float sum = 0.f, sq = 0.f;
#pragma unroll
    for (int k = 0; k < 4; k++) {
        v[k] = xr[threadIdx.x + 256 * k];
        sum += v[k];
        sq  += v[k] * v[k];
    }
#pragma unroll
    for (int o = 16; o > 0; o >>= 1) {
        sum += __shfl_xor_sync(0xffffffffu, sum, o);
        sq  += __shfl_xor_sync(0xffffffffu, sq, o);
    }
    __shared__ float ssum[8], ssq[8], s_mu, s_rinv;
    int wid = threadIdx.x >> 5, lid = threadIdx.x & 31;
    if (lid == 0) { ssum[wid] = sum; ssq[wid] = sq; }
    __syncthreads();
    if (threadIdx.x == 0) {
        float ts = 0.f, tq = 0.f;
#pragma unroll
        for (int i = 0; i < 8; i++) { ts += ssum[i]; tq += ssq[i]; }
        float mu  = ts * (1.0f / DM);
        float var = tq * (1.0f / DM) - mu * mu;
        s_mu = mu; s_rinv = rsqrtf(var + 1e-5f);
    }
    __syncthreads();
    float mu = s_mu, rinv = s_rinv;
#pragma unroll
    for (int k = 0; k < 4; k++) {
        int c = threadIdx.x + 256 * k;
        float val = (v[k] - mu) * rinv * w[c] + b[c];
        __nv_bfloat16 h, l;
        split_f(val, h, l);
        ohi[(size_t)row * DM + c] = h;
        olo[(size_t)row * DM + c] = l;
    }
}

// ---------------- mma.sync GEMM: C[M,N] = A[M,K] @ W[N,K]^T ----------------
#define BK 32
#define MAT_B (128 * 40 * 2)           // 10240 bytes per matrix tile (80B rows)
#define STG_B (4 * MAT_B)
#define SMEM_TOT (2 * STG_B)

__global__ __launch_bounds__(256, 1) void gemm_mma(
    const __nv_bfloat16* __restrict__ Ah, const __nv_bfloat16* __restrict__ Al,
    const __nv_bfloat16* __restrict__ Wh, const __nv_bfloat16* __restrict__ Wl,
    const float* __restrict__ bias, const float* __restrict__ res,
    float* __restrict__ C,
    __nv_bfloat16* __restrict__ Chi, __nv_bfloat16* __restrict__ Clo,
    int N, int K, int do_gelu)
{
    extern __shared__ char smem[];
    uint32_t sbase = smem_u32(smem);
    int t = threadIdx.x;
    int w = t >> 5, lane = t & 31;
    int warp_m = w & 1, warp_n = w >> 1;
    int lr = lane & 15, lh = lane >> 4;

    int row0 = blockIdx.y * 128;
    int col0 = blockIdx.x * 128;
    const __nv_bfloat16* srcs[4] = {
        Ah + (size_t)row0 * K, Al + (size_t)row0 * K,
        Wh + (size_t)col0 * K, Wl + (size_t)col0 * K };

    float acc[4][4][4];
#pragma unroll
    for (int i = 0; i < 4; i++)
#pragma unroll
        for (int j = 0; j < 4; j++)
#pragma unroll
            for (int q = 0; q < 4; q++) acc[i][j][q] = 0.f;

    int niter = K / BK;

    {
        uint32_t sst = sbase;
#pragma unroll
        for (int c8 = 0; c8 < 8; c8++) {
            int c = c8 * 256 + t;
            int mat = c >> 9, rem = c & 511, r = rem >> 2, q = rem & 3;
            CP_ASYNC16(sst + mat * MAT_B + r * 80 + q * 16,
                       srcs[mat] + (size_t)r * K + q * 8);
        }
        CP_COMMIT();
    }

    for (int it = 0; it < niter; it++) {
        if (it + 1 < niter) {
            uint32_t sst = sbase + ((it + 1) & 1) * STG_B;
            int k0 = (it + 1) * BK;
#pragma unroll
            for (int c8 = 0; c8 < 8; c8++) {
                int c = c8 * 256 + t;
                int mat = c >> 9, rem = c & 511, r = rem >> 2, q = rem & 3;
                CP_ASYNC16(sst + mat * MAT_B + r * 80 + q * 16,
                           srcs[mat] + (size_t)r * K + k0 + q * 8);
            }
        }
        CP_COMMIT();
        CP_WAIT1();
        __syncthreads();

        uint32_t sst = sbase + (it & 1) * STG_B;
#pragma unroll
        for (int ks = 0; ks < 2; ks++) {
            uint32_t coff = ks * 32 + lh * 16;
            uint32_t ah[4][4], al[4][4], bh[2][4], bl[2][4];
#pragma unroll
            for (int mt = 0; mt < 4; mt++) {
                uint32_t rofs = (warp_m * 64 + mt * 16 + lr) * 80 + coff;
                ldsm4(ah[mt], sst + rofs);
                ldsm4(al[mt], sst + MAT_B + rofs);
            }
#pragma unroll
            for (int p = 0; p < 2; p++) {
                uint32_t rofs = (warp_n * 32 + p * 16 + lr) * 80 + coff;
                ldsm4(bh[p], sst + 2 * MAT_B + rofs);
                ldsm4(bl[p], sst + 3 * MAT_B + rofs);
            }
#pragma unroll
            for (int mt = 0; mt < 4; mt++)
#pragma unroll
                for (int nt = 0; nt < 4; nt++) {
                    int p = nt >> 1, o = nt & 1;
                    mma16816(acc[mt][nt], ah[mt], bh[p][o], bh[p][o + 2]);
                }
#pragma unroll
            for (int mt = 0; mt < 4; mt++)
#pragma unroll
                for (int nt = 0; nt < 4; nt++) {
                    int p = nt >> 1, o = nt & 1;
                    mma16816(acc[mt][nt], ah[mt], bl[p][o], bl[p][o + 2]);
                }
#pragma unroll
            for (int mt = 0; mt < 4; mt++)
#pragma unroll
                for (int nt = 0; nt < 4; nt++) {
                    int p = nt >> 1, o = nt & 1;
                    mma16816(acc[mt][nt], al[mt], bh[p][o], bh[p][o + 2]);
                }
        }
        __syncthreads();
    }

    int g = lane >> 2, tig = lane & 3;
#pragma unroll
    for (int mt = 0; mt < 4; mt++) {
#pragma unroll
        for (int nt = 0; nt < 4; nt++) {
            int col = col0 + warp_n * 32 + nt * 8 + tig * 2;
            float b0 = 0.f, b1 = 0.f;
            if (bias) { b0 = bias[col]; b1 = bias[col + 1]; }
#pragma unroll
            for (int hrow = 0; hrow < 2; hrow++) {
                int row = row0 + warp_m * 64 + mt * 16 + g + hrow * 8;
                float vx = acc[mt][nt][hrow * 2]     + b0;
                float vy = acc[mt][nt][hrow * 2 + 1] + b1;
                if (do_gelu) {
                    vx = 0.5f * vx * (1.f + erff(vx * 0.70710678f));
                    vy = 0.5f * vy * (1.f + erff(vy * 0.70710678f));
                }
                if (res) {
                    vx += res[(size_t)row * N + col];
                    vy += res[(size_t)row * N + col + 1];
                }
                if (C) {
                    *(float2*)(C + (size_t)row * N + col) = make_float2(vx, vy);
                }
                if (Chi) {
                    __nv_bfloat16 hx, lx, hy, ly;
                    split_f(vx, hx, lx); split_f(vy, hy, ly);
                    *(__nv_bfloat162*)(Chi + (size_t)row * N + col) = __nv_bfloat162(hx, hy);
                    *(__nv_bfloat162*)(Clo + (size_t)row * N + col) = __nv_bfloat162(lx, ly);
                }
            }
        }
    }
}

// ---------------- tensor-core causal flash attention ----------------
// BM=64 q-rows/CTA, 4 warps x 16 rows; kv tiles of 64 double-buffered.
// Full split precision: S = Qh*Kh + Qh*Kl + Ql*Kh ; O += Ph*Vh + Ph*Vl + Pl*Vh
#define ARS   144                     // smem row bytes (64*2 + 16 pad)
#define ATB   (64 * ARS)              // 9216 per matrix
#define AQ_B  (2 * ATB)               // Qh, Ql
#define ASTG  (4 * ATB)               // Kh, Kl, Vh, Vl
#define ASM_TOT (AQ_B + 2 * ASTG)     // 92160

__global__ __launch_bounds__(128) void attn_mma(
    const __nv_bfloat16* __restrict__ qkvh, const __nv_bfloat16* __restrict__ qkvl,
    __nv_bfloat16* __restrict__ ohi, __nv_bfloat16* __restrict__ olo)
{
    extern __shared__ char smem[];
    uint32_t sb = smem_u32(smem);
    int t = threadIdx.x, w = t >> 5, lane = t & 31;
    int qt = blockIdx.x, head = blockIdx.y, b = blockIdx.z;
    int q0 = qt * 64;

    // ldmatrix x4 address patterns (relative row/col within a 16x16 block)
    int a_row = (lane & 7) + ((lane & 8) ? 8 : 0);    // a-style / V-trans
    int a_cb  = (lane & 16) ? 16 : 0;
    int b_row = (lane & 7) + ((lane & 16) ? 8 : 0);   // K b-style (no trans)
    int b_cb  = (lane & 8) ? 16 : 0;

    // ---- load Q (hi/lo) ----
#pragma unroll
    for (int i = 0; i < 8; i++) {
        int c = i * 128 + t;
        int mat = c >> 9, rem = c & 511, r = rem >> 3, c16 = rem & 7;
        const __nv_bfloat16* src = (mat ? qkvl : qkvh) +
            ((size_t)(b * SEQ + q0 + r) * (3 * DM) + head * 64 + c16 * 8);
        CP_ASYNC16(sb + mat * ATB + r * ARS + c16 * 16, src);
    }
    CP_COMMIT();

    // ---- prefetch kv tile 0 ----
    {
        uint32_t sst = sb + AQ_B;
#pragma unroll
        for (int i = 0; i < 16; i++) {
            int c = i * 128 + t;
            int mat = c >> 9, rem = c & 511, r = rem >> 3, c16 = rem & 7;
            const __nv_bfloat16* base = (mat & 1) ? qkvl : qkvh;
            int off = (mat >> 1) ? 2 * DM : DM;
            const __nv_bfloat16* src = base +
                ((size_t)(b * SEQ + r) * (3 * DM) + off + head * 64 + c16 * 8);
            CP_ASYNC16(sst + mat * ATB + r * ARS + c16 * 16, src);
        }
        CP_COMMIT();
    }

    uint32_t qa_h[4][4], qa_l[4][4];
    float of[8][4];
#pragma unroll
    for (int f = 0; f < 8; f++)
#pragma unroll
        for (int q = 0; q < 4; q++) of[f][q] = 0.f;
    float m0 = -1e30f, m1 = -1e30f, l0 = 0.f, l1 = 0.f;

    int row_in0 = (lane >> 2);          // 0..7
    int colb2   = 2 * (lane & 3);       // 0,2,4,6

    for (int kt = 0; kt <= qt; kt++) {
        // prefetch next
        if (kt < qt) {
            uint32_t sst = sb + AQ_B + ((kt + 1) & 1) * ASTG;
            int k0n = (kt + 1) * 64;
#pragma unroll
            for (int i = 0; i < 16; i++) {
                int c = i * 128 + t;
                int mat = c >> 9, rem = c & 511, r = rem >> 3, c16 = rem & 7;
                const __nv_bfloat16* base = (mat & 1) ? qkvl : qkvh;
                int off = (mat >> 1) ? 2 * DM : DM;
                const __nv_bfloat16* src = base +
                    ((size_t)(b * SEQ + k0n + r) * (3 * DM) + off + head * 64 + c16 * 8);
                CP_ASYNC16(sst + mat * ATB + r * ARS + c16 * 16, src);
            }
        }
        CP_COMMIT();
        CP_WAIT1();
        __syncthreads();

        if (kt == 0) {
            // load Q fragments once
#pragma unroll
            for (int ks = 0; ks < 4; ks++) {
                uint32_t ao = (uint32_t)((w * 16 + a_row) * ARS + ks * 32 + a_cb);
                ldsm4(qa_h[ks], sb + ao);
                ldsm4(qa_l[ks], sb + ATB + ao);
            }
        }

        uint32_t kst = sb + AQ_B + (kt & 1) * ASTG;

        // ---- S = Q K^T (3 passes) ----
        float sf[8][4];
#pragma unroll
        for (int f = 0; f < 8; f++)
#pragma unroll
            for (int q = 0; q < 4; q++) sf[f][q] = 0.f;

#pragma unroll
        for (int ks = 0; ks < 4; ks++) {
#pragma unroll
            for (int nb = 0; nb < 4; nb++) {
                uint32_t ko = (uint32_t)((nb * 16 + b_row) * ARS + ks * 32 + b_cb);
                uint32_t kh4[4], kl4[4];
                ldsm4(kh4, kst + ko);
                ldsm4(kl4, kst + ATB + ko);
                mma16816(sf[2 * nb],     qa_h[ks], kh4[0], kh4[1]);
                mma16816(sf[2 * nb + 1], qa_h[ks], kh4[2], kh4[3]);
                mma16816(sf[2 * nb],     qa_h[ks], kl4[0], kl4[1]);
                mma16816(sf[2 * nb + 1], qa_h[ks], kl4[2], kl4[3]);
                mma16816(sf[2 * nb],     qa_l[ks], kh4[0], kh4[1]);
                mma16816(sf[2 * nb + 1], qa_l[ks], kh4[2], kh4[3]);
            }
        }

        // ---- scale + causal mask ----
        int r0 = q0 + w * 16 + row_in0;
        int r1 = r0 + 8;
        int k0 = kt * 64;
#pragma unroll
        for (int f = 0; f < 8; f++) {
#pragma unroll
            for (int q = 0; q < 4; q++) sf[f][q] *= 0.125f;
            if (kt == qt) {
                int c0 = k0 + f * 8 + colb2;
                if (c0 > r0)     sf[f][0] = -1e30f;
                if (c0 + 1 > r0) sf[f][1] = -1e30f;
                if (c0 > r1)     sf[f][2] = -1e30f;
                if (c0 + 1 > r1) sf[f][3] = -1e30f;
            }
        }

        // ---- online softmax ----
        float mx0 = -1e30f, mx1 = -1e30f;
#pragma unroll
        for (int f = 0; f < 8; f++) {
            mx0 = fmaxf(mx0, fmaxf(sf[f][0], sf[f][1]));
            mx1 = fmaxf(mx1, fmaxf(sf[f][2], sf[f][3]));
        }
        mx0 = fmaxf(mx0, __shfl_xor_sync(0xffffffffu, mx0, 1));
        mx0 = fmaxf(mx0, __shfl_xor_sync(0xffffffffu, mx0, 2));
        mx1 = fmaxf(mx1, __shfl_xor_sync(0xffffffffu, mx1, 1));
        mx1 = fmaxf(mx1, __shfl_xor_sync(0xffffffffu, mx1, 2));
        float mn0 = fmaxf(m0, mx0), mn1 = fmaxf(m1, mx1);
        float cr0 = __expf(m0 - mn0), cr1 = __expf(m1 - mn1);
        m0 = mn0; m1 = mn1;
        l0 *= cr0; l1 *= cr1;
#pragma unroll
        for (int f = 0; f < 8; f++) {
            of[f][0] *= cr0; of[f][1] *= cr0;
            of[f][2] *= cr1; of[f][3] *= cr1;
        }

        uint32_t ph[4][4], pl[4][4];
#pragma unroll
        for (int f = 0; f < 8; f++) {
            float p0 = __expf(sf[f][0] - mn0);
            float p1 = __expf(sf[f][1] - mn0);
            float p2 = __expf(sf[f][2] - mn1);
            float p3 = __expf(sf[f][3] - mn1);
            l0 += p0 + p1;
            l1 += p2 + p3;
            __nv_bfloat16 h0, lo0, h1, lo1, h2, lo2, h3, lo3;
            split_f(p0, h0, lo0); split_f(p1, h1, lo1);
            split_f(p2, h2, lo2); split_f(p3, h3, lo3);
            int ks = f >> 1, o = (f & 1) * 2;
            __nv_bfloat162 hp01(h0, h1), hp23(h2, h3);
            __nv_bfloat162 lp01(lo0, lo1), lp23(lo2, lo3);
            ph[ks][o]     = *(uint32_t*)&hp01;
            ph[ks][o + 1] = *(uint32_t*)&hp23;
            pl[ks][o]     = *(uint32_t*)&lp01;
            pl[ks][o + 1] = *(uint32_t*)&lp23;
        }

        // ---- O += P V (3 passes) ----
        uint32_t vst = kst + 2 * ATB;
#pragma unroll
        for (int ks = 0; ks < 4; ks++) {
#pragma unroll
            for (int nb = 0; nb < 4; nb++) {
                uint32_t vo = (uint32_t)((ks * 16 + a_row) * ARS + nb * 32 + a_cb);
                uint32_t vh4[4], vl4[4];
                ldsm4t(vh4, vst + vo);
                ldsm4t(vl4, vst + ATB + vo);
                mma16816(of[2 * nb],     ph[ks], vh4[0], vh4[1]);
                mma16816(of[2 * nb + 1], ph[ks], vh4[2], vh4[3]);
                mma16816(of[2 * nb],     ph[ks], vl4[0], vl4[1]);
                mma16816(of[2 * nb + 1], ph[ks], vl4[2], vl4[3]);
                mma16816(of[2 * nb],     pl[ks], vh4[0], vh4[1]);
                mma16816(of[2 * nb + 1], pl[ks], vh4[2], vh4[3]);
            }
        }
        __syncthreads();
    }

    // ---- finalize ----
    l0 += __shfl_xor_sync(0xffffffffu, l0, 1);
    l0 += __shfl_xor_sync(0xffffffffu, l0, 2);
    l1 += __shfl_xor_sync(0xffffffffu, l1, 1);
    l1 += __shfl_xor_sync(0xffffffffu, l1, 2);
    float i0 = 1.f / l0, i1 = 1.f / l1;

    int r0g = b * SEQ + q0 + w * 16 + row_in0;
#pragma unroll
    for (int f = 0; f < 8; f++) {
        int col = head * 64 + f * 8 + colb2;
        float v0 = of[f][0] * i0, v1 = of[f][1] * i0;
        float v2 = of[f][2] * i1, v3 = of[f][3] * i1;
        __nv_bfloat16 h0, lo0, h1, lo1, h2, lo2, h3, lo3;
        split_f(v0, h0, lo0); split_f(v1, h1, lo1);
        split_f(v2, h2, lo2); split_f(v3, h3, lo3);
        *(__nv_bfloat162*)(ohi + (size_t)r0g * DM + col)       = __nv_bfloat162(h0, h1);
        *(__nv_bfloat162*)(olo + (size_t)r0g * DM + col)       = __nv_bfloat162(lo0, lo1);
        *(__nv_bfloat162*)(ohi + (size_t)(r0g + 8) * DM + col) = __nv_bfloat162(h2, h3);
        *(__nv_bfloat162*)(olo + (size_t)(r0g + 8) * DM + col) = __nv_bfloat162(lo2, lo3);
    }
}

// ---------------- host ----------------
extern "C" void kernel_launch(void* const* d_in, const int* in_sizes, int n_in,
                              void* d_out, int out_size)
{
    const float* x      = (const float*)d_in[0];
    const float* ln1_w  = (const float*)d_in[1];
    const float* ln1_b  = (const float*)d_in[2];
    const float* ln2_w  = (const float*)d_in[3];
    const float* ln2_b  = (const float*)d_in[4];
    const float* qkv_w  = (const float*)d_in[5];
    const float* o_w    = (const float*)d_in[6];
    const float* ffn_w1 = (const float*)d_in[7];
    const float* ffn_b1 = (const float*)d_in[8];
    const float* ffn_w2 = (const float*)d_in[9];
    const float* ffn_b2 = (const float*)d_in[10];
    float* out = (float*)d_out;

    float* x1;
    cudaGetSymbolAddress((void**)&x1, g_x1);
    __nv_bfloat16 *qw_h, *qw_l, *ow_h, *ow_l, *w1_h, *w1_l, *w2_h, *w2_l;
    __nv_bfloat16 *h_h, *h_l, *qkv_h, *qkv_l, *at_h, *at_l, *h2_h, *h2_l, *f1_h, *f1_l;
    cudaGetSymbolAddress((void**)&qw_h, g_qkvw_hi); cudaGetSymbolAddress((void**)&qw_l, g_qkvw_lo);
    cudaGetSymbolAddress((void**)&ow_h, g_ow_hi);   cudaGetSymbolAddress((void**)&ow_l, g_ow_lo);
    cudaGetSymbolAddress((void**)&w1_h, g_w1_hi);   cudaGetSymbolAddress((void**)&w1_l, g_w1_lo);
    cudaGetSymbolAddress((void**)&w2_h, g_w2_hi);   cudaGetSymbolAddress((void**)&w2_l, g_w2_lo);
    cudaGetSymbolAddress((void**)&h_h,  g_h_hi);    cudaGetSymbolAddress((void**)&h_l,  g_h_lo);
    cudaGetSymbolAddress((void**)&qkv_h, g_qkv_hi); cudaGetSymbolAddress((void**)&qkv_l, g_qkv_lo);
    cudaGetSymbolAddress((void**)&at_h, g_at_hi);   cudaGetSymbolAddress((void**)&at_l, g_at_lo);
    cudaGetSymbolAddress((void**)&h2_h, g_h2_hi);   cudaGetSymbolAddress((void**)&h2_l, g_h2_lo);
    cudaGetSymbolAddress((void**)&f1_h, g_f1_hi);   cudaGetSymbolAddress((void**)&f1_l, g_f1_lo);

    cudaFuncSetAttribute(gemm_mma, cudaFuncAttributeMaxDynamicSharedMemorySize, SMEM_TOT);
    cudaFuncSetAttribute(attn_mma, cudaFuncAttributeMaxDynamicSharedMemorySize, ASM_TOT);

    auto splitN = [&](const float* src, __nv_bfloat16* hi, __nv_bfloat16* lo, int n) {
        split4<<<n / 1024, 256>>>((const float4*)src, (__nv_bfloat162*)hi, (__nv_bfloat162*)lo, n / 4);
    };

    splitN(qkv_w,  qw_h, qw_l, 3 * DM * DM);
    splitN(o_w,    ow_h, ow_l, DM * DM);
    splitN(ffn_w1, w1_h, w1_l, 4 * DM * DM);
    splitN(ffn_w2, w2_h, w2_l, 4 * DM * DM);

    // h = LN1(x) -> hi/lo
    ln_split<<<TOK, 256>>>(x, ln1_w, ln1_b, h_h, h_l);
    // qkv = h @ qkv_w^T -> hi/lo
    gemm_mma<<<dim3(3 * DM / 128, TOK / 128), 256, SMEM_TOT>>>(h_h, h_l, qw_h, qw_l,
        nullptr, nullptr, nullptr, qkv_h, qkv_l, 3 * DM, DM, 0);
    // attention -> hi/lo
    attn_mma<<<dim3(SEQ / 64, NHEAD, 2), 128, ASM_TOT>>>(qkv_h, qkv_l, at_h, at_l);
    // x1 = x + attn @ o_w^T (fp32)
    gemm_mma<<<dim3(DM / 128, TOK / 128), 256, SMEM_TOT>>>(at_h, at_l, ow_h, ow_l,
        nullptr, x, x1, nullptr, nullptr, DM, DM, 0);
    // h2 = LN2(x1) -> hi/lo
    ln_split<<<TOK, 256>>>(x1, ln2_w, ln2_b, h2_h, h2_l);
    // ff1 = gelu(h2 @ ffn_w1^T + b1) -> hi/lo
    gemm_mma<<<dim3(4 * DM / 128, TOK / 128), 256, SMEM_TOT>>>(h2_h, h2_l, w1_h, w1_l,
        ffn_b1, nullptr, nullptr, f1_h, f1_l, 4 * DM, DM, 1);
    // out = x1 + ff1 @ ffn_w2^T + b2 (fp32)
    gemm_mma<<<dim3(DM / 128, TOK / 128), 256, SMEM_TOT>>>(f1_h, f1_l, w2_h, w2_l,
        ffn_b2, x1, out, nullptr, nullptr, DM, 4 * DM, 0);
}

// round 14
// speedup vs baseline: 2.6080x; 2.6009x over previous
#include <cuda_runtime.h>
#include <cuda_fp16.h>
#include <math.h>
#include <stdint.h>

#define TOK 4096      // B*N = 2*2048
#define DM  1024
#define SEQ 2048
#define NHEAD 16

// ---------------- scratch (no cudaMalloc allowed) ----------------
__device__ float g_x1 [TOK * DM];

__device__ __half g_qkvw[3 * DM * DM];
__device__ __half g_ow  [DM * DM];
__device__ __half g_w1  [4 * DM * DM];
__device__ __half g_w2  [4 * DM * DM];
__device__ __half g_h   [TOK * DM];
__device__ __half g_qkv [TOK * 3 * DM];
__device__ __half g_at  [TOK * DM];
__device__ __half g_h2  [TOK * DM];
__device__ __half g_f1  [TOK * 4 * DM];

// ---------------- helpers ----------------
__device__ __forceinline__ uint32_t smem_u32(const void* p) {
    uint32_t a;
    asm("{ .reg .u64 t; cvta.to.shared.u64 t, %1; cvt.u32.u64 %0, t; }" : "=r"(a) : "l"(p));
    return a;
}
#define CP_ASYNC16(sa, ga) \
    asm volatile("cp.async.cg.shared.global [%0], [%1], 16;" :: "r"(sa), "l"(ga))
#define CP_COMMIT() asm volatile("cp.async.commit_group;" ::: "memory")
#define CP_WAIT1()  asm volatile("cp.async.wait_group 1;" ::: "memory")

__device__ __forceinline__ void ldsm4(uint32_t* r, uint32_t addr) {
    asm volatile("ldmatrix.sync.aligned.m8n8.x4.shared.b16 {%0,%1,%2,%3}, [%4];"
                 : "=r"(r[0]), "=r"(r[1]), "=r"(r[2]), "=r"(r[3]) : "r"(addr));
}
__device__ __forceinline__ void ldsm4t(uint32_t* r, uint32_t addr) {
    asm volatile("ldmatrix.sync.aligned.m8n8.x4.trans.shared.b16 {%0,%1,%2,%3}, [%4];"
                 : "=r"(r[0]), "=r"(r[1]), "=r"(r[2]), "=r"(r[3]) : "r"(addr));
}
__device__ __forceinline__ void mma16816(float* d, const uint32_t* a, uint32_t b0, uint32_t b1) {
    asm volatile("mma.sync.aligned.m16n8k16.row.col.f32.f16.f16.f32 "
                 "{%0,%1,%2,%3}, {%4,%5,%6,%7}, {%8,%9}, {%0,%1,%2,%3};"
                 : "+f"(d[0]), "+f"(d[1]), "+f"(d[2]), "+f"(d[3])
                 : "r"(a[0]), "r"(a[1]), "r"(a[2]), "r"(a[3]), "r"(b0), "r"(b1));
}
__device__ __forceinline__ uint32_t pack_h2(float a, float b) {
    __half2 h = __floats2half2_rn(a, b);
    return *(uint32_t*)&h;
}

// ---------------- fp32 -> fp16 convert (weights) ----------------
__global__ __launch_bounds__(256) void cvt4(const float4* __restrict__ in,
                                            __half2* __restrict__ o, int n4)
{
    int i = blockIdx.x * 256 + threadIdx.x;
    if (i >= n4) return;
    float4 x = in[i];
    o[2 * i]     = __floats2half2_rn(x.x, x.y);
    o[2 * i + 1] = __floats2half2_rn(x.z, x.w);
}

// ---------------- LayerNorm -> fp16 ----------------
__global__ __launch_bounds__(256) void ln_half(const float* __restrict__ x,
                                               const float* __restrict__ w,
                                               const float* __restrict__ b,
                                               __half* __restrict__ oh)
{
    int row = blockIdx.x;
    const float* xr = x + (size_t)row * DM;
    float v[4];
    float sum = 0.f, sq = 0.f;
#pragma unroll
    for (int k = 0; k < 4; k++) {
        v[k] = xr[threadIdx.x + 256 * k];
        sum += v[k];
        sq  += v[k] * v[k];
    }
#pragma unroll
    for (int o = 16; o > 0; o >>= 1) {
        sum += __shfl_xor_sync(0xffffffffu, sum, o);
        sq  += __shfl_xor_sync(0xffffffffu, sq, o);
    }
    __shared__ float ssum[8], ssq[8], s_mu, s_rinv;
    int wid = threadIdx.x >> 5, lid = threadIdx.x & 31;
    if (lid == 0) { ssum[wid] = sum; ssq[wid] = sq; }
    __syncthreads();
    if (threadIdx.x == 0) {
        float ts = 0.f, tq = 0.f;
#pragma unroll
        for (int i = 0; i < 8; i++) { ts += ssum[i]; tq += ssq[i]; }
        float mu  = ts * (1.0f / DM);
        float var = tq * (1.0f / DM) - mu * mu;
        s_mu = mu; s_rinv = rsqrtf(var + 1e-5f);
    }
    __syncthreads();
    float mu = s_mu, rinv = s_rinv;
#pragma unroll
    for (int k = 0; k < 4; k++) {
        int c = threadIdx.x + 256 * k;
        float val = (v[k] - mu) * rinv * w[c] + b[c];
        oh[(size_t)row * DM + c] = __float2half_rn(val);
    }
}

// ---------------- fp16 mma GEMM: C[M,N] = A[M,K] @ W[N,K]^T ----------------
#define BK 32
#define MAT_B (128 * 80)               // 128 rows x 80B (32 halfs + 16B pad)
#define STG_B (2 * MAT_B)              // A + W
#define SMEM_TOT (2 * STG_B)           // 40960

__global__ __launch_bounds__(256, 2) void gemm_mma(
    const __half* __restrict__ A, const __half* __restrict__ W,
    const float* __restrict__ bias, const float* __restrict__ res,
    float* __restrict__ C, __half* __restrict__ Ch,
    int N, int K, int do_gelu)
{
    extern __shared__ char smem[];
    uint32_t sbase = smem_u32(smem);
    int t = threadIdx.x;
    int w = t >> 5, lane = t & 31;
    int warp_m = w & 1, warp_n = w >> 1;      // 2x4: 64 x 32 per warp
    int lr = lane & 15, lh = lane >> 4;

    int row0 = blockIdx.y * 128;
    int col0 = blockIdx.x * 128;
    const __half* srcs[2] = { A + (size_t)row0 * K, W + (size_t)col0 * K };

    float acc[4][4][4];
#pragma unroll
    for (int i = 0; i < 4; i++)
#pragma unroll
        for (int j = 0; j < 4; j++)
#pragma unroll
            for (int q = 0; q < 4; q++) acc[i][j][q] = 0.f;

    int niter = K / BK;

    {
#pragma unroll
        for (int c4 = 0; c4 < 4; c4++) {
            int c = c4 * 256 + t;                    // 0..1023
            int mat = c >> 9, rem = c & 511, r = rem >> 2, q = rem & 3;
            CP_ASYNC16(sbase + mat * MAT_B + r * 80 + q * 16,
                       srcs[mat] + (size_t)r * K + q * 8);
        }
        CP_COMMIT();
    }

    for (int it = 0; it < niter; it++) {
        if (it + 1 < niter) {
            uint32_t sst = sbase + ((it + 1) & 1) * STG_B;
            int k0 = (it + 1) * BK;
#pragma unroll
            for (int c4 = 0; c4 < 4; c4++) {
                int c = c4 * 256 + t;
                int mat = c >> 9, rem = c & 511, r = rem >> 2, q = rem & 3;
                CP_ASYNC16(sst + mat * MAT_B + r * 80 + q * 16,
                           srcs[mat] + (size_t)r * K + k0 + q * 8);
            }
        }
        CP_COMMIT();
        CP_WAIT1();
        __syncthreads();

        uint32_t sst = sbase + (it & 1) * STG_B;
#pragma unroll
        for (int ks = 0; ks < 2; ks++) {
            uint32_t coff = ks * 32 + lh * 16;
            uint32_t ah[4][4], bh[2][4];
#pragma unroll
            for (int mt = 0; mt < 4; mt++) {
                uint32_t rofs = (warp_m * 64 + mt * 16 + lr) * 80 + coff;
                ldsm4(ah[mt], sst + rofs);
            }
#pragma unroll
            for (int p = 0; p < 2; p++) {
                uint32_t rofs = (warp_n * 32 + p * 16 + lr) * 80 + coff;
                ldsm4(bh[p], sst + MAT_B + rofs);
            }
#pragma unroll
            for (int mt = 0; mt < 4; mt++)
#pragma unroll
                for (int nt = 0; nt < 4; nt++) {
                    int p = nt >> 1, o = nt & 1;
                    mma16816(acc[mt][nt], ah[mt], bh[p][o], bh[p][o + 2]);
                }
        }
        __syncthreads();
    }

    int g = lane >> 2, tig = lane & 3;
#pragma unroll
    for (int mt = 0; mt < 4; mt++) {
#pragma unroll
        for (int nt = 0; nt < 4; nt++) {
            int col = col0 + warp_n * 32 + nt * 8 + tig * 2;
            float b0 = 0.f, b1 = 0.f;
            if (bias) { b0 = bias[col]; b1 = bias[col + 1]; }
#pragma unroll
            for (int hrow = 0; hrow < 2; hrow++) {
                int row = row0 + warp_m * 64 + mt * 16 + g + hrow * 8;
                float vx = acc[mt][nt][hrow * 2]     + b0;
                float vy = acc[mt][nt][hrow * 2 + 1] + b1;
                if (do_gelu) {
                    vx = 0.5f * vx * (1.f + erff(vx * 0.70710678f));
                    vy = 0.5f * vy * (1.f + erff(vy * 0.70710678f));
                }
                if (res) {
                    vx += res[(size_t)row * N + col];
                    vy += res[(size_t)row * N + col + 1];
                }
                if (C)
                    *(float2*)(C + (size_t)row * N + col) = make_float2(vx, vy);
                if (Ch)
                    *(uint32_t*)(Ch + (size_t)row * N + col) = pack_h2(vx, vy);
            }
        }
    }
}

// ---------------- fp16 tensor-core causal flash attention ----------------
// BM=64 q-rows/CTA, 4 warps x 16 rows; kv tiles of 64 double-buffered.
#define ARS   144                     // smem row bytes (64*2 + 16 pad)
#define ATB   (64 * ARS)              // 9216 per matrix
#define ASTG  (2 * ATB)               // K, V
#define ASM_TOT (ATB + 2 * ASTG)      // 46080

__global__ __launch_bounds__(128, 2) void attn_mma(
    const __half* __restrict__ qkv, __half* __restrict__ oh)
{
    extern __shared__ char smem[];
    uint32_t sb = smem_u32(smem);
    int t = threadIdx.x, w = t >> 5, lane = t & 31;
    int qt = blockIdx.x, head = blockIdx.y, b = blockIdx.z;
    int q0 = qt * 64;

    int a_row = (lane & 7) + ((lane & 8) ? 8 : 0);    // a-style / V-trans
    int a_cb  = (lane & 16) ? 16 : 0;
    int b_row = (lane & 7) + ((lane & 16) ? 8 : 0);   // K b-style
    int b_cb  = (lane & 8) ? 16 : 0;

    // ---- load Q ----
#pragma unroll
    for (int i = 0; i < 4; i++) {
        int c = i * 128 + t;                  // 0..511
        int r = c >> 3, c16 = c & 7;
        const __half* src = qkv +
            ((size_t)(b * SEQ + q0 + r) * (3 * DM) + head * 64 + c16 * 8);
        CP_ASYNC16(sb + r * ARS + c16 * 16, src);
    }
    CP_COMMIT();

    // ---- prefetch kv tile 0 ----
    {
        uint32_t sst = sb + ATB;
#pragma unroll
        for (int i = 0; i < 8; i++) {
            int c = i * 128 + t;              // 0..1023
            int mat = c >> 9, rem = c & 511, r = rem >> 3, c16 = rem & 7;
            int off = mat ? 2 * DM : DM;
            const __half* src = qkv +
                ((size_t)(b * SEQ + r) * (3 * DM) + off + head * 64 + c16 * 8);
            CP_ASYNC16(sst + mat * ATB + r * ARS + c16 * 16, src);
        }
        CP_COMMIT();
    }

    uint32_t qa[4][4];
    float of[8][4];
#pragma unroll
    for (int f = 0; f < 8; f++)
#pragma unroll
        for (int q = 0; q < 4; q++) of[f][q] = 0.f;
    float m0 = -1e30f, m1 = -1e30f, l0 = 0.f, l1 = 0.f;

    int row_in0 = (lane >> 2);
    int colb2   = 2 * (lane & 3);

    for (int kt = 0; kt <= qt; kt++) {
        if (kt < qt) {
            uint32_t sst = sb + ATB + ((kt + 1) & 1) * ASTG;
            int k0n = (kt + 1) * 64;
#pragma unroll
            for (int i = 0; i < 8; i++) {
                int c = i * 128 + t;
                int mat = c >> 9, rem = c & 511, r = rem >> 3, c16 = rem & 7;
                int off = mat ? 2 * DM : DM;
                const __half* src = qkv +
                    ((size_t)(b * SEQ + k0n + r) * (3 * DM) + off + head * 64 + c16 * 8);
                CP_ASYNC16(sst + mat * ATB + r * ARS + c16 * 16, src);
            }
        }
        CP_COMMIT();
        CP_WAIT1();
        __syncthreads();

        if (kt == 0) {
#pragma unroll
            for (int ks = 0; ks < 4; ks++) {
                uint32_t ao = (uint32_t)((w * 16 + a_row) * ARS + ks * 32 + a_cb);
                ldsm4(qa[ks], sb + ao);
            }
        }

        uint32_t kst = sb + ATB + (kt & 1) * ASTG;

        // ---- S = Q K^T ----
        float sf[8][4];
#pragma unroll
        for (int f = 0; f < 8; f++)
#pragma unroll
            for (int q = 0; q < 4; q++) sf[f][q] = 0.f;

#pragma unroll
        for (int ks = 0; ks < 4; ks++) {
#pragma unroll
            for (int nb = 0; nb < 4; nb++) {
                uint32_t ko = (uint32_t)((nb * 16 + b_row) * ARS + ks * 32 + b_cb);
                uint32_t kh4[4];
                ldsm4(kh4, kst + ko);
                mma16816(sf[2 * nb],     qa[ks], kh4[0], kh4[1]);
                mma16816(sf[2 * nb + 1], qa[ks], kh4[2], kh4[3]);
            }
        }

        // ---- scale + causal mask ----
        int r0 = q0 + w * 16 + row_in0;
        int r1 = r0 + 8;
        int k0 = kt * 64;
#pragma unroll
        for (int f = 0; f < 8; f++) {
#pragma unroll
            for (int q = 0; q < 4; q++) sf[f][q] *= 0.125f;
            if (kt == qt) {
                int c0 = k0 + f * 8 + colb2;
                if (c0 > r0)     sf[f][0] = -1e30f;
                if (c0 + 1 > r0) sf[f][1] = -1e30f;
                if (c0 > r1)     sf[f][2] = -1e30f;
                if (c0 + 1 > r1) sf[f][3] = -1e30f;
            }
        }

        // ---- online softmax ----
        float mx0 = -1e30f, mx1 = -1e30f;
#pragma unroll
        for (int f = 0; f < 8; f++) {
            mx0 = fmaxf(mx0, fmaxf(sf[f][0], sf[f][1]));
            mx1 = fmaxf(mx1, fmaxf(sf[f][2], sf[f][3]));
        }
        mx0 = fmaxf(mx0, __shfl_xor_sync(0xffffffffu, mx0, 1));
        mx0 = fmaxf(mx0, __shfl_xor_sync(0xffffffffu, mx0, 2));
        mx1 = fmaxf(mx1, __shfl_xor_sync(0xffffffffu, mx1, 1));
        mx1 = fmaxf(mx1, __shfl_xor_sync(0xffffffffu, mx1, 2));
        float mn0 = fmaxf(m0, mx0), mn1 = fmaxf(m1, mx1);
        float cr0 = __expf(m0 - mn0), cr1 = __expf(m1 - mn1);
        m0 = mn0; m1 = mn1;
        l0 *= cr0; l1 *= cr1;
#pragma unroll
        for (int f = 0; f < 8; f++) {
            of[f][0] *= cr0; of[f][1] *= cr0;
            of[f][2] *= cr1; of[f][3] *= cr1;
        }

        uint32_t ph[4][4];
#pragma unroll
        for (int f = 0; f < 8; f++) {
            float p0 = __expf(sf[f][0] - mn0);
            float p1 = __expf(sf[f][1] - mn0);
            float p2 = __expf(sf[f][2] - mn1);
            float p3 = __expf(sf[f][3] - mn1);
            l0 += p0 + p1;
            l1 += p2 + p3;
            int ks = f >> 1, o = (f & 1) * 2;
            ph[ks][o]     = pack_h2(p0, p1);
            ph[ks][o + 1] = pack_h2(p2, p3);
        }

        // ---- O += P V ----
        uint32_t vst = kst + ATB;
#pragma unroll
        for (int ks = 0; ks < 4; ks++) {
#pragma unroll
            for (int nb = 0; nb < 4; nb++) {
                uint32_t vo = (uint32_t)((ks * 16 + a_row) * ARS + nb * 32 + a_cb);
                uint32_t vh4[4];
                ldsm4t(vh4, vst + vo);
                mma16816(of[2 * nb],     ph[ks], vh4[0], vh4[1]);
                mma16816(of[2 * nb + 1], ph[ks], vh4[2], vh4[3]);
            }
        }
        __syncthreads();
    }

    // ---- finalize ----
    l0 += __shfl_xor_sync(0xffffffffu, l0, 1);
    l0 += __shfl_xor_sync(0xffffffffu, l0, 2);
    l1 += __shfl_xor_sync(0xffffffffu, l1, 1);
    l1 += __shfl_xor_sync(0xffffffffu, l1, 2);
    float i0 = 1.f / l0, i1 = 1.f / l1;

    int r0g = b * SEQ + q0 + w * 16 + row_in0;
#pragma unroll
    for (int f = 0; f < 8; f++) {
        int col = head * 64 + f * 8 + colb2;
        *(uint32_t*)(oh + (size_t)r0g * DM + col) =
            pack_h2(of[f][0] * i0, of[f][1] * i0);
        *(uint32_t*)(oh + (size_t)(r0g + 8) * DM + col) =
            pack_h2(of[f][2] * i1, of[f][3] * i1);
    }
}

// ---------------- host ----------------
extern "C" void kernel_launch(void* const* d_in, const int* in_sizes, int n_in,
                              void* d_out, int out_size)
{
    const float* x      = (const float*)d_in[0];
    const float* ln1_w  = (const float*)d_in[1];
    const float* ln1_b  = (const float*)d_in[2];
    const float* ln2_w  = (const float*)d_in[3];
    const float* ln2_b  = (const float*)d_in[4];
    const float* qkv_w  = (const float*)d_in[5];
    const float* o_w    = (const float*)d_in[6];
    const float* ffn_w1 = (const float*)d_in[7];
    const float* ffn_b1 = (const float*)d_in[8];
    const float* ffn_w2 = (const float*)d_in[9];
    const float* ffn_b2 = (const float*)d_in[10];
    float* out = (float*)d_out;

    float* x1;
    cudaGetSymbolAddress((void**)&x1, g_x1);
    __half *qw, *ow, *w1, *w2, *h, *qkv, *at, *h2, *f1;
    cudaGetSymbolAddress((void**)&qw,  g_qkvw);
    cudaGetSymbolAddress((void**)&ow,  g_ow);
    cudaGetSymbolAddress((void**)&w1,  g_w1);
    cudaGetSymbolAddress((void**)&w2,  g_w2);
    cudaGetSymbolAddress((void**)&h,   g_h);
    cudaGetSymbolAddress((void**)&qkv, g_qkv);
    cudaGetSymbolAddress((void**)&at,  g_at);
    cudaGetSymbolAddress((void**)&h2,  g_h2);
    cudaGetSymbolAddress((void**)&f1,  g_f1);

    cudaFuncSetAttribute(gemm_mma, cudaFuncAttributeMaxDynamicSharedMemorySize, SMEM_TOT);
    cudaFuncSetAttribute(attn_mma, cudaFuncAttributeMaxDynamicSharedMemorySize, ASM_TOT);

    auto cvtN = [&](const float* src, __half* dst, int n) {
        cvt4<<<n / 1024, 256>>>((const float4*)src, (__half2*)dst, n / 4);
    };

    cvtN(qkv_w,  qw, 3 * DM * DM);
    cvtN(o_w,    ow, DM * DM);
    cvtN(ffn_w1, w1, 4 * DM * DM);
    cvtN(ffn_w2, w2, 4 * DM * DM);

    // h = LN1(x) -> fp16
    ln_half<<<TOK, 256>>>(x, ln1_w, ln1_b, h);
    // qkv = h @ qkv_w^T -> fp16
    gemm_mma<<<dim3(3 * DM / 128, TOK / 128), 256, SMEM_TOT>>>(h, qw,
        nullptr, nullptr, nullptr, qkv, 3 * DM, DM, 0);
    // attention -> fp16
    attn_mma<<<dim3(SEQ / 64, NHEAD, 2), 128, ASM_TOT>>>(qkv, at);
    // x1 = x + attn @ o_w^T (fp32)
    gemm_mma<<<dim3(DM / 128, TOK / 128), 256, SMEM_TOT>>>(at, ow,
        nullptr, x, x1, nullptr, DM, DM, 0);
    // h2 = LN2(x1) -> fp16
    ln_half<<<TOK, 256>>>(x1, ln2_w, ln2_b, h2);
    // ff1 = gelu(h2 @ ffn_w1^T + b1) -> fp16
    gemm_mma<<<dim3(4 * DM / 128, TOK / 128), 256, SMEM_TOT>>>(h2, w1,
        ffn_b1, nullptr, nullptr, f1, 4 * DM, DM, 1);
    // out = x1 + ff1 @ ffn_w2^T + b2 (fp32)
    gemm_mma<<<dim3(DM / 128, TOK / 128), 256, SMEM_TOT>>>(f1, w2,
        ffn_b2, x1, out, nullptr, DM, 4 * DM, 0);
}

// round 17
// speedup vs baseline: 2.8343x; 1.0867x over previous
#include <cuda_runtime.h>
#include <cuda_fp16.h>
#include <math.h>
#include <stdint.h>

#define TOK 4096      // B*N = 2*2048
#define DM  1024
#define SEQ 2048
#define NHEAD 16

// ---------------- scratch (no cudaMalloc allowed) ----------------
__device__ float g_x1 [TOK * DM];

__device__ __half g_qkvw[3 * DM * DM];
__device__ __half g_ow  [DM * DM];
__device__ __half g_w1  [4 * DM * DM];
__device__ __half g_w2  [4 * DM * DM];
__device__ __half g_h   [TOK * DM];
__device__ __half g_qkv [TOK * 3 * DM];
__device__ __half g_at  [TOK * DM];
__device__ __half g_h2  [TOK * DM];
__device__ __half g_f1  [TOK * 4 * DM];

// ---------------- helpers ----------------
__device__ __forceinline__ uint32_t smem_u32(const void* p) {
    uint32_t a;
    asm("{ .reg .u64 t; cvta.to.shared.u64 t, %1; cvt.u32.u64 %0, t; }" : "=r"(a) : "l"(p));
    return a;
}
#define CP_ASYNC16(sa, ga) \
    asm volatile("cp.async.cg.shared.global [%0], [%1], 16;" :: "r"(sa), "l"(ga))
#define CP_COMMIT() asm volatile("cp.async.commit_group;" ::: "memory")
#define CP_WAIT1()  asm volatile("cp.async.wait_group 1;" ::: "memory")

__device__ __forceinline__ void ldsm4(uint32_t* r, uint32_t addr) {
    asm volatile("ldmatrix.sync.aligned.m8n8.x4.shared.b16 {%0,%1,%2,%3}, [%4];"
                 : "=r"(r[0]), "=r"(r[1]), "=r"(r[2]), "=r"(r[3]) : "r"(addr));
}
__device__ __forceinline__ void ldsm4t(uint32_t* r, uint32_t addr) {
    asm volatile("ldmatrix.sync.aligned.m8n8.x4.trans.shared.b16 {%0,%1,%2,%3}, [%4];"
                 : "=r"(r[0]), "=r"(r[1]), "=r"(r[2]), "=r"(r[3]) : "r"(addr));
}
__device__ __forceinline__ void mma16816(float* d, const uint32_t* a, uint32_t b0, uint32_t b1) {
    asm volatile("mma.sync.aligned.m16n8k16.row.col.f32.f16.f16.f32 "
                 "{%0,%1,%2,%3}, {%4,%5,%6,%7}, {%8,%9}, {%0,%1,%2,%3};"
                 : "+f"(d[0]), "+f"(d[1]), "+f"(d[2]), "+f"(d[3])
                 : "r"(a[0]), "r"(a[1]), "r"(a[2]), "r"(a[3]), "r"(b0), "r"(b1));
}
__device__ __forceinline__ uint32_t pack_h2(float a, float b) {
    __half2 h = __floats2half2_rn(a, b);
    return *(uint32_t*)&h;
}

// ---------------- fp32 -> fp16 convert (weights) ----------------
__global__ __launch_bounds__(256) void cvt4(const float4* __restrict__ in,
                                            __half2* __restrict__ o, int n4)
{
    int i = blockIdx.x * 256 + threadIdx.x;
    if (i >= n4) return;
    float4 x = in[i];
    o[2 * i]     = __floats2half2_rn(x.x, x.y);
    o[2 * i + 1] = __floats2half2_rn(x.z, x.w);
}

// ---------------- LayerNorm -> fp16 ----------------
__global__ __launch_bounds__(256) void ln_half(const float* __restrict__ x,
                                               const float* __restrict__ w,
                                               const float* __restrict__ b,
                                               __half* __restrict__ oh)
{
    int row = blockIdx.x;
    const float* xr = x + (size_t)row * DM;
    float v[4];
    float sum = 0.f, sq = 0.f;
#pragma unroll
    for (int k = 0; k < 4; k++) {
        v[k] = xr[threadIdx.x + 256 * k];
        sum += v[k];
        sq  += v[k] * v[k];
    }
#pragma unroll
    for (int o = 16; o > 0; o >>= 1) {
        sum += __shfl_xor_sync(0xffffffffu, sum, o);
        sq  += __shfl_xor_sync(0xffffffffu, sq, o);
    }
    __shared__ float ssum[8], ssq[8], s_mu, s_rinv;
    int wid = threadIdx.x >> 5, lid = threadIdx.x & 31;
    if (lid == 0) { ssum[wid] = sum; ssq[wid] = sq; }
    __syncthreads();
    if (threadIdx.x == 0) {
        float ts = 0.f, tq = 0.f;
#pragma unroll
        for (int i = 0; i < 8; i++) { ts += ssum[i]; tq += ssq[i]; }
        float mu  = ts * (1.0f / DM);
        float var = tq * (1.0f / DM) - mu * mu;
        s_mu = mu; s_rinv = rsqrtf(var + 1e-5f);
    }
    __syncthreads();
    float mu = s_mu, rinv = s_rinv;
#pragma unroll
    for (int k = 0; k < 4; k++) {
        int c = threadIdx.x + 256 * k;
        float val = (v[k] - mu) * rinv * w[c] + b[c];
        oh[(size_t)row * DM + c] = __float2half_rn(val);
    }
}

// ---------------- fp16 mma GEMM: C[M,N] = A[M,K] @ W[N,K]^T ----------------
// CTA 128x128, BK=64, 4 warps x (64x64) warp tiles, double-buffered cp.async.
#define BK 64
#define GRS 144                        // smem row bytes: 64 halfs + 16B pad
#define MAT_B (128 * GRS)              // 18432 per matrix
#define STG_B (2 * MAT_B)              // A + W = 36864
#define SMEM_TOT (2 * STG_B)           // 73728

__global__ __launch_bounds__(128, 2) void gemm_mma(
    const __half* __restrict__ A, const __half* __restrict__ W,
    const float* __restrict__ bias, const float* __restrict__ res,
    float* __restrict__ C, __half* __restrict__ Ch,
    int N, int K, int do_gelu)
{
    extern __shared__ char smem[];
    uint32_t sbase = smem_u32(smem);
    int t = threadIdx.x;
    int w = t >> 5, lane = t & 31;
    int warp_m = w & 1, warp_n = w >> 1;      // 2x2: 64 x 64 per warp
    int lr = lane & 15, lh = lane >> 4;

    int row0 = blockIdx.y * 128;
    int col0 = blockIdx.x * 128;
    const __half* srcs[2] = { A + (size_t)row0 * K, W + (size_t)col0 * K };

    float acc[4][8][4];
#pragma unroll
    for (int i = 0; i < 4; i++)
#pragma unroll
        for (int j = 0; j < 8; j++)
#pragma unroll
            for (int q = 0; q < 4; q++) acc[i][j][q] = 0.f;

    int niter = K / BK;

    // fill stage 0: 2048 chunks of 16B, 128 threads -> 16 per thread
    {
#pragma unroll
        for (int i = 0; i < 16; i++) {
            int c = i * 128 + t;
            int mat = c >> 10, rem = c & 1023, r = rem >> 3, q = rem & 7;
            CP_ASYNC16(sbase + mat * MAT_B + r * GRS + q * 16,
                       srcs[mat] + (size_t)r * K + q * 8);
        }
        CP_COMMIT();
    }

    for (int it = 0; it < niter; it++) {
        if (it + 1 < niter) {
            uint32_t sst = sbase + ((it + 1) & 1) * STG_B;
            int k0 = (it + 1) * BK;
#pragma unroll
            for (int i = 0; i < 16; i++) {
                int c = i * 128 + t;
                int mat = c >> 10, rem = c & 1023, r = rem >> 3, q = rem & 7;
                CP_ASYNC16(sst + mat * MAT_B + r * GRS + q * 16,
                           srcs[mat] + (size_t)r * K + k0 + q * 8);
            }
        }
        CP_COMMIT();
        CP_WAIT1();
        __syncthreads();

        uint32_t sst = sbase + (it & 1) * STG_B;
#pragma unroll
        for (int ks = 0; ks < 4; ks++) {
            uint32_t coff = ks * 32 + lh * 16;
            uint32_t ah[4][4], bh[4][4];
#pragma unroll
            for (int mt = 0; mt < 4; mt++) {
                uint32_t rofs = (warp_m * 64 + mt * 16 + lr) * GRS + coff;
                ldsm4(ah[mt], sst + rofs);
            }
#pragma unroll
            for (int p = 0; p < 4; p++) {
                uint32_t rofs = (warp_n * 64 + p * 16 + lr) * GRS + coff;
                ldsm4(bh[p], sst + MAT_B + rofs);
            }
#pragma unroll
            for (int mt = 0; mt < 4; mt++)
#pragma unroll
                for (int nb = 0; nb < 8; nb++) {
                    int p = nb >> 1, o = nb & 1;
                    mma16816(acc[mt][nb], ah[mt], bh[p][o], bh[p][o + 2]);
                }
        }
        __syncthreads();
    }

    int g = lane >> 2, tig = lane & 3;
#pragma unroll
    for (int mt = 0; mt < 4; mt++) {
#pragma unroll
        for (int nb = 0; nb < 8; nb++) {
            int col = col0 + warp_n * 64 + nb * 8 + tig * 2;
            float b0 = 0.f, b1 = 0.f;
            if (bias) { b0 = bias[col]; b1 = bias[col + 1]; }
#pragma unroll
            for (int hrow = 0; hrow < 2; hrow++) {
                int row = row0 + warp_m * 64 + mt * 16 + g + hrow * 8;
                float vx = acc[mt][nb][hrow * 2]     + b0;
                float vy = acc[mt][nb][hrow * 2 + 1] + b1;
                if (do_gelu) {
                    vx = 0.5f * vx * (1.f + erff(vx * 0.70710678f));
                    vy = 0.5f * vy * (1.f + erff(vy * 0.70710678f));
                }
                if (res) {
                    vx += res[(size_t)row * N + col];
                    vy += res[(size_t)row * N + col + 1];
                }
                if (C)
                    *(float2*)(C + (size_t)row * N + col) = make_float2(vx, vy);
                if (Ch)
                    *(uint32_t*)(Ch + (size_t)row * N + col) = pack_h2(vx, vy);
            }
        }
    }
}

// ---------------- fp16 tensor-core causal flash attention ----------------
#define ARS   144                     // smem row bytes (64*2 + 16 pad)
#define ATB   (64 * ARS)              // 9216 per matrix
#define ASTG  (2 * ATB)               // K, V
#define ASM_TOT (ATB + 2 * ASTG)      // 46080

__global__ __launch_bounds__(128, 2) void attn_mma(
    const __half* __restrict__ qkv, __half* __restrict__ oh)
{
    extern __shared__ char smem[];
    uint32_t sb = smem_u32(smem);
    int t = threadIdx.x, w = t >> 5, lane = t & 31;
    int qt = blockIdx.x, head = blockIdx.y, b = blockIdx.z;
    int q0 = qt * 64;

    int a_row = (lane & 7) + ((lane & 8) ? 8 : 0);    // a-style / V-trans
    int a_cb  = (lane & 16) ? 16 : 0;
    int b_row = (lane & 7) + ((lane & 16) ? 8 : 0);   // K b-style
    int b_cb  = (lane & 8) ? 16 : 0;

    // ---- load Q ----
#pragma unroll
    for (int i = 0; i < 4; i++) {
        int c = i * 128 + t;
        int r = c >> 3, c16 = c & 7;
        const __half* src = qkv +
            ((size_t)(b * SEQ + q0 + r) * (3 * DM) + head * 64 + c16 * 8);
        CP_ASYNC16(sb + r * ARS + c16 * 16, src);
    }
    CP_COMMIT();

    // ---- prefetch kv tile 0 ----
    {
        uint32_t sst = sb + ATB;
#pragma unroll
        for (int i = 0; i < 8; i++) {
            int c = i * 128 + t;
            int mat = c >> 9, rem = c & 511, r = rem >> 3, c16 = rem & 7;
            int off = mat ? 2 * DM : DM;
            const __half* src = qkv +
                ((size_t)(b * SEQ + r) * (3 * DM) + off + head * 64 + c16 * 8);
            CP_ASYNC16(sst + mat * ATB + r * ARS + c16 * 16, src);
        }
        CP_COMMIT();
    }

    uint32_t qa[4][4];
    float of[8][4];
#pragma unroll
    for (int f = 0; f < 8; f++)
#pragma unroll
        for (int q = 0; q < 4; q++) of[f][q] = 0.f;
    float m0 = -1e30f, m1 = -1e30f, l0 = 0.f, l1 = 0.f;

    int row_in0 = (lane >> 2);
    int colb2   = 2 * (lane & 3);

    for (int kt = 0; kt <= qt; kt++) {
        if (kt < qt) {
            uint32_t sst = sb + ATB + ((kt + 1) & 1) * ASTG;
            int k0n = (kt + 1) * 64;
#pragma unroll
            for (int i = 0; i < 8; i++) {
                int c = i * 128 + t;
                int mat = c >> 9, rem = c & 511, r = rem >> 3, c16 = rem & 7;
                int off = mat ? 2 * DM : DM;
                const __half* src = qkv +
                    ((size_t)(b * SEQ + k0n + r) * (3 * DM) + off + head * 64 + c16 * 8);
                CP_ASYNC16(sst + mat * ATB + r * ARS + c16 * 16, src);
            }
        }
        CP_COMMIT();
        CP_WAIT1();
        __syncthreads();

        if (kt == 0) {
#pragma unroll
            for (int ks = 0; ks < 4; ks++) {
                uint32_t ao = (uint32_t)((w * 16 + a_row) * ARS + ks * 32 + a_cb);
                ldsm4(qa[ks], sb + ao);
            }
        }

        uint32_t kst = sb + ATB + (kt & 1) * ASTG;

        // ---- S = Q K^T ----
        float sf[8][4];
#pragma unroll
        for (int f = 0; f < 8; f++)
#pragma unroll
            for (int q = 0; q < 4; q++) sf[f][q] = 0.f;

#pragma unroll
        for (int ks = 0; ks < 4; ks++) {
#pragma unroll
            for (int nb = 0; nb < 4; nb++) {
                uint32_t ko = (uint32_t)((nb * 16 + b_row) * ARS + ks * 32 + b_cb);
                uint32_t kh4[4];
                ldsm4(kh4, kst + ko);
                mma16816(sf[2 * nb],     qa[ks], kh4[0], kh4[1]);
                mma16816(sf[2 * nb + 1], qa[ks], kh4[2], kh4[3]);
            }
        }

        // ---- scale + causal mask ----
        int r0 = q0 + w * 16 + row_in0;
        int r1 = r0 + 8;
        int k0 = kt * 64;
#pragma unroll
        for (int f = 0; f < 8; f++) {
#pragma unroll
            for (int q = 0; q < 4; q++) sf[f][q] *= 0.125f;
            if (kt == qt) {
                int c0 = k0 + f * 8 + colb2;
                if (c0 > r0)     sf[f][0] = -1e30f;
                if (c0 + 1 > r0) sf[f][1] = -1e30f;
                if (c0 > r1)     sf[f][2] = -1e30f;
                if (c0 + 1 > r1) sf[f][3] = -1e30f;
            }
        }

        // ---- online softmax ----
        float mx0 = -1e30f, mx1 = -1e30f;
#pragma unroll
        for (int f = 0; f < 8; f++) {
            mx0 = fmaxf(mx0, fmaxf(sf[f][0], sf[f][1]));
            mx1 = fmaxf(mx1, fmaxf(sf[f][2], sf[f][3]));
        }
        mx0 = fmaxf(mx0, __shfl_xor_sync(0xffffffffu, mx0, 1));
        mx0 = fmaxf(mx0, __shfl_xor_sync(0xffffffffu, mx0, 2));
        mx1 = fmaxf(mx1, __shfl_xor_sync(0xffffffffu, mx1, 1));
        mx1 = fmaxf(mx1, __shfl_xor_sync(0xffffffffu, mx1, 2));
        float mn0 = fmaxf(m0, mx0), mn1 = fmaxf(m1, mx1);
        float cr0 = __expf(m0 - mn0), cr1 = __expf(m1 - mn1);
        m0 = mn0; m1 = mn1;
        l0 *= cr0; l1 *= cr1;
#pragma unroll
        for (int f = 0; f < 8; f++) {
            of[f][0] *= cr0; of[f][1] *= cr0;
            of[f][2] *= cr1; of[f][3] *= cr1;
        }

        uint32_t ph[4][4];
#pragma unroll
        for (int f = 0; f < 8; f++) {
            float p0 = __expf(sf[f][0] - mn0);
            float p1 = __expf(sf[f][1] - mn0);
            float p2 = __expf(sf[f][2] - mn1);
            float p3 = __expf(sf[f][3] - mn1);
            l0 += p0 + p1;
            l1 += p2 + p3;
            int ks = f >> 1, o = (f & 1) * 2;
            ph[ks][o]     = pack_h2(p0, p1);
            ph[ks][o + 1] = pack_h2(p2, p3);
        }

        // ---- O += P V ----
        uint32_t vst = kst + ATB;
#pragma unroll
        for (int ks = 0; ks < 4; ks++) {
#pragma unroll
            for (int nb = 0; nb < 4; nb++) {
                uint32_t vo = (uint32_t)((ks * 16 + a_row) * ARS + nb * 32 + a_cb);
                uint32_t vh4[4];
                ldsm4t(vh4, vst + vo);
                mma16816(of[2 * nb],     ph[ks], vh4[0], vh4[1]);
                mma16816(of[2 * nb + 1], ph[ks], vh4[2], vh4[3]);
            }
        }
        __syncthreads();
    }

    // ---- finalize ----
    l0 += __shfl_xor_sync(0xffffffffu, l0, 1);
    l0 += __shfl_xor_sync(0xffffffffu, l0, 2);
    l1 += __shfl_xor_sync(0xffffffffu, l1, 1);
    l1 += __shfl_xor_sync(0xffffffffu, l1, 2);
    float i0 = 1.f / l0, i1 = 1.f / l1;

    int r0g = b * SEQ + q0 + w * 16 + row_in0;
#pragma unroll
    for (int f = 0; f < 8; f++) {
        int col = head * 64 + f * 8 + colb2;
        *(uint32_t*)(oh + (size_t)r0g * DM + col) =
            pack_h2(of[f][0] * i0, of[f][1] * i0);
        *(uint32_t*)(oh + (size_t)(r0g + 8) * DM + col) =
            pack_h2(of[f][2] * i1, of[f][3] * i1);
    }
}

// ---------------- host ----------------
extern "C" void kernel_launch(void* const* d_in, const int* in_sizes, int n_in,
                              void* d_out, int out_size)
{
    const float* x      = (const float*)d_in[0];
    const float* ln1_w  = (const float*)d_in[1];
    const float* ln1_b  = (const float*)d_in[2];
    const float* ln2_w  = (const float*)d_in[3];
    const float* ln2_b  = (const float*)d_in[4];
    const float* qkv_w  = (const float*)d_in[5];
    const float* o_w    = (const float*)d_in[6];
    const float* ffn_w1 = (const float*)d_in[7];
    const float* ffn_b1 = (const float*)d_in[8];
    const float* ffn_w2 = (const float*)d_in[9];
    const float* ffn_b2 = (const float*)d_in[10];
    float* out = (float*)d_out;

    float* x1;
    cudaGetSymbolAddress((void**)&x1, g_x1);
    __half *qw, *ow, *w1, *w2, *h, *qkv, *at, *h2, *f1;
    cudaGetSymbolAddress((void**)&qw,  g_qkvw);
    cudaGetSymbolAddress((void**)&ow,  g_ow);
    cudaGetSymbolAddress((void**)&w1,  g_w1);
    cudaGetSymbolAddress((void**)&w2,  g_w2);
    cudaGetSymbolAddress((void**)&h,   g_h);
    cudaGetSymbolAddress((void**)&qkv, g_qkv);
    cudaGetSymbolAddress((void**)&at,  g_at);
    cudaGetSymbolAddress((void**)&h2,  g_h2);
    cudaGetSymbolAddress((void**)&f1,  g_f1);

    cudaFuncSetAttribute(gemm_mma, cudaFuncAttributeMaxDynamicSharedMemorySize, SMEM_TOT);
    cudaFuncSetAttribute(attn_mma, cudaFuncAttributeMaxDynamicSharedMemorySize, ASM_TOT);

    auto cvtN = [&](const float* src, __half* dst, int n) {
        cvt4<<<n / 1024, 256>>>((const float4*)src, (__half2*)dst, n / 4);
    };

    cvtN(qkv_w,  qw, 3 * DM * DM);
    cvtN(o_w,    ow, DM * DM);
    cvtN(ffn_w1, w1, 4 * DM * DM);
    cvtN(ffn_w2, w2, 4 * DM * DM);

    // h = LN1(x) -> fp16
    ln_half<<<TOK, 256>>>(x, ln1_w, ln1_b, h);
    // qkv = h @ qkv_w^T -> fp16
    gemm_mma<<<dim3(3 * DM / 128, TOK / 128), 128, SMEM_TOT>>>(h, qw,
        nullptr, nullptr, nullptr, qkv, 3 * DM, DM, 0);
    // attention -> fp16
    attn_mma<<<dim3(SEQ / 64, NHEAD, 2), 128, ASM_TOT>>>(qkv, at);
    // x1 = x + attn @ o_w^T (fp32)
    gemm_mma<<<dim3(DM / 128, TOK / 128), 128, SMEM_TOT>>>(at, ow,
        nullptr, x, x1, nullptr, DM, DM, 0);
    // h2 = LN2(x1) -> fp16
    ln_half<<<TOK, 256>>>(x1, ln2_w, ln2_b, h2);
    // ff1 = gelu(h2 @ ffn_w1^T + b1) -> fp16
    gemm_mma<<<dim3(4 * DM / 128, TOK / 128), 128, SMEM_TOT>>>(h2, w1,
        ffn_b1, nullptr, nullptr, f1, 4 * DM, DM, 1);
    // out = x1 + ff1 @ ffn_w2^T + b2 (fp32)
    gemm_mma<<<dim3(DM / 128, TOK / 128), 128, SMEM_TOT>>>(f1, w2,
        ffn_b2, x1, out, nullptr, DM, 4 * DM, 0);
}